// round 13
// baseline (speedup 1.0000x reference)
#include <cuda_runtime.h>
#include <cuda_bf16.h>
#include <cuda_fp16.h>
#include <cstdint>
#include <cstddef>

#define BS   4
#define SEQ  2048
#define DIM  256
#define HH   4
#define HD   1024
#define BHN  16

// ======================= device scratch =======================
__device__ __align__(256) __half g_xhf [(size_t)BS*SEQ*DIM];      // x fp16 split hi
__device__ __align__(256) __half g_xlf [(size_t)BS*SEQ*DIM];      // x fp16 split lo
__device__ __align__(256) __half g_xTf [(size_t)BS*DIM*SEQ];      // x^T fp16 single
__device__ __align__(256) __half g_wqktf[(size_t)2*HD*DIM];       // Wq^T | Wk^T fp16
__device__ __align__(256) __half g_wvtf[(size_t)DIM*HD];          // Wv^T fp16 single
__device__ __align__(256) __half g_QKf [(size_t)2*BHN*SEQ*DIM];   // Qf | Kf (fp16)
__device__ __align__(256) __half g_Pf  [(size_t)BHN*SEQ*SEQ];     // fp16 probs for PV
__device__ __align__(256) __half g_attf[(size_t)BS*SEQ*HD];       // att fp16 single
__device__ __align__(256) float  g_out_fb [(size_t)BS*SEQ*DIM];
__device__ __align__(256) float  g_probs_fb[(size_t)BHN*SEQ*SEQ];

// ======================= helpers =======================
__device__ __forceinline__ uint32_t smem_u32(const void* p) {
    uint32_t a;
    asm("{ .reg .u64 t; cvta.to.shared.u64 t, %1; cvt.u32.u64 %0, t; }" : "=r"(a) : "l"(p));
    return a;
}
#define CP16(dst, src) \
    asm volatile("cp.async.cg.shared.global [%0], [%1], 16;" :: "r"(dst), "l"(src))
#define CP_COMMIT() asm volatile("cp.async.commit_group;" ::: "memory")
#define CP_WAIT0()  asm volatile("cp.async.wait_group 0;" ::: "memory")
#define CP_WAIT1()  asm volatile("cp.async.wait_group 1;" ::: "memory")

#define LDSM4(r0, r1, r2, r3, a) \
    asm volatile("ldmatrix.sync.aligned.m8n8.x4.shared.b16 {%0,%1,%2,%3}, [%4];" \
        : "=r"(r0), "=r"(r1), "=r"(r2), "=r"(r3) : "r"(a))

#define MMA_FP16(d, a, b) \
    asm volatile("mma.sync.aligned.m16n8k16.row.col.f32.f16.f16.f32 " \
        "{%0,%1,%2,%3}, {%4,%5,%6,%7}, {%8,%9}, {%0,%1,%2,%3};" \
        : "+f"((d)[0]), "+f"((d)[1]), "+f"((d)[2]), "+f"((d)[3]) \
        : "r"((a)[0]), "r"((a)[1]), "r"((a)[2]), "r"((a)[3]), \
          "r"((b)[0]), "r"((b)[1]))

// ======================= fused prep kernel =======================
__global__ void k_prep(const float* __restrict__ x, const float* __restrict__ Wq,
                       const float* __restrict__ Wk, const float* __restrict__ Wv,
                       __half* __restrict__ xhf, __half* __restrict__ xlf,
                       __half* __restrict__ xTf,
                       __half* __restrict__ wqktf, __half* __restrict__ wvtf)
{
    int b = blockIdx.x;
    const int tid = threadIdx.x;
    if (b < 1024) {
        int i0 = b * 2048 + tid;
#pragma unroll
        for (int q = 0; q < 8; ++q) {
            int i = i0 + q * 256;
            float v = x[i];
            __half h = __float2half_rn(v);
            __half l = __float2half_rn(v - __half2float(h));
            xhf[i] = h; xlf[i] = l;
        }
        return;
    }
    b -= 1024;
    const float* in; int R, C, bx, by;
    __half* oh;
    if (b < 256)      { in = Wq; oh = wqktf; R = 256;  C = 1024; bx = b & 31; by = b >> 5; }
    else if (b < 512) { b -= 256; in = Wk; oh = wqktf + (size_t)HD * DIM;
                        R = 256; C = 1024; bx = b & 31; by = b >> 5; }
    else if (b < 768) { b -= 512; in = Wv; oh = wvtf; R = 1024; C = 256; bx = b & 7; by = b >> 3; }
    else {
        b -= 768;
        int z = b >> 9, t = b & 511;
        in = x + (size_t)z * SEQ * DIM;
        oh = xTf + (size_t)z * DIM * SEQ;
        R = 2048; C = 256; bx = t & 7; by = t >> 3;
    }

    __shared__ float tbuf[32][33];
    const int tx = tid & 31, ty = tid >> 5;
    const int c0 = bx * 32, r0 = by * 32;
#pragma unroll
    for (int i = 0; i < 4; ++i)
        tbuf[ty + i * 8][tx] = in[(size_t)(r0 + ty + i * 8) * C + c0 + tx];
    __syncthreads();
#pragma unroll
    for (int i = 0; i < 4; ++i) {
        float v = tbuf[tx][ty + i * 8];
        oh[(size_t)(c0 + ty + i * 8) * R + r0 + tx] = __float2half_rn(v);
    }
}

// ============ 256-thread GEMM (proj MODE 4 / wv+LN MODE 3), Kc=64 ============
template<int MODE, int BN>
__global__ void __launch_bounds__(256, (BN == 256) ? 1 : 2)
k_mma(const uint8_t* __restrict__ Ah, const uint8_t* __restrict__ Al,
      const uint8_t* __restrict__ Bh,
      int lda, int ldb, int K,
      size_t strideAz, size_t strideBz, int bShift,
      float* __restrict__ ep_f, void* __restrict__ ep_a,
      const float* __restrict__ resid,
      const float* __restrict__ gamma, const float* __restrict__ beta,
      size_t strideEz)
{
    constexpr bool PROJ   = (MODE == 4);
    constexpr int  WNT    = BN / 4;
    constexpr int  NBN    = BN / 32;
    constexpr int  NBL    = BN / 64;
    constexpr int  STAGE  = PROJ ? 49152 : (16384 + BN * 128);
    constexpr int  NSTAGE = 2;
    extern __shared__ __align__(1024) char smem[];
    const uint32_t sb = smem_u32(smem);
    const int tid = threadIdx.x;
    const int wid = tid >> 5, lane = tid & 31;
    const int wm = wid >> 2, wn = wid & 3;
    const int mBase = blockIdx.y * 128, nBase = blockIdx.x * BN;
    const int z = blockIdx.z;

    const uint8_t* A0 = Ah + (size_t)z * strideAz * 2;
    const uint8_t* A1 = PROJ ? Al + (size_t)z * strideAz * 2 : nullptr;
    const uint8_t* B0 = Bh + (size_t)(z >> bShift) * strideBz * 2;

    const int nch = K >> 6;

#define LOAD_TILE(srcB, ldE, rowB, k0, dstOff, ROWS)                                  \
    { _Pragma("unroll") for (int p_ = 0; p_ < (ROWS) / 32; ++p_) {                    \
        int idx_ = tid + 256 * p_;                                                    \
        int row_ = idx_ >> 3, c16_ = idx_ & 7;                                        \
        const uint8_t* g_ = (srcB) +                                                  \
            ((size_t)((rowB) + row_) * (ldE) + (k0) + c16_ * 8) * 2;                  \
        uint32_t d_ = sb + (dstOff) + row_ * 128 +                                    \
                      ((c16_ * 16) ^ ((row_ & 7) << 4));                              \
        CP16(d_, g_); } }

#define LOAD_CHUNK(i_, s_)                                                            \
    {                                                                                 \
        const int k0_ = (i_) * 64;                                                    \
        const int so_ = (s_) * STAGE;                                                 \
        if (PROJ) {                                                                   \
            LOAD_TILE(A0, lda, mBase, k0_, so_, 128);                                 \
            LOAD_TILE(A1, lda, mBase, k0_, so_ + 16384, 128);                         \
            LOAD_TILE(B0, ldb, nBase, k0_, so_ + 32768, 128);                         \
        } else {                                                                      \
            LOAD_TILE(A0, lda, mBase, k0_, so_, 128);                                 \
            LOAD_TILE(B0, ldb, nBase, k0_, so_ + 16384, BN);                          \
        }                                                                             \
        CP_COMMIT();                                                                  \
    }

    const int lrow = (lane & 7) + ((lane >> 3) & 1) * 8;
    const int kh16 = ((lane >> 4) & 1) * 16;
    const int swz  = (lane & 7) << 4;
    int rA[4], rB[NBL];
#pragma unroll
    for (int bm = 0; bm < 4; ++bm) rA[bm] = (wm * 64 + bm * 16 + lrow) * 128;
#pragma unroll
    for (int nb = 0; nb < NBL; ++nb) rB[nb] = (wn * WNT + nb * 16 + lrow) * 128;

    float acc[4][NBN][4];
#pragma unroll
    for (int a = 0; a < 4; ++a)
#pragma unroll
        for (int b = 0; b < NBN; ++b)
#pragma unroll
            for (int c = 0; c < 4; ++c) acc[a][b][c] = 0.f;

#pragma unroll
    for (int p = 0; p < NSTAGE - 1; ++p)
        if (p < nch) LOAD_CHUNK(p, p);

    int st = 0;
    for (int i = 0; i < nch; ++i) {
        CP_WAIT0();
        __syncthreads();
        if (i + NSTAGE - 1 < nch) {
            int s2 = st + NSTAGE - 1; if (s2 >= NSTAGE) s2 -= NSTAGE;
            LOAD_CHUNK(i + NSTAGE - 1, s2);
        }

        const uint32_t so = sb + st * STAGE;
        const uint32_t sA  = so;
        const uint32_t sAl = so + 16384;
        const uint32_t sB  = so + (PROJ ? 32768 : 16384);

#pragma unroll
        for (int ks = 0; ks < 4; ++ks) {
            const int cz = ((ks * 32) + kh16) ^ swz;
            uint32_t ah[4][4];
#pragma unroll
            for (int bm = 0; bm < 4; ++bm)
                LDSM4(ah[bm][0], ah[bm][1], ah[bm][2], ah[bm][3], sA + rA[bm] + cz);
            uint32_t bh[NBN][2];
#pragma unroll
            for (int nb = 0; nb < NBL; ++nb) {
                uint32_t t0, t1, t2, t3;
                LDSM4(t0, t1, t2, t3, sB + rB[nb] + cz);
                bh[nb * 2][0] = t0; bh[nb * 2][1] = t2;
                bh[nb * 2 + 1][0] = t1; bh[nb * 2 + 1][1] = t3;
            }
#pragma unroll
            for (int bm = 0; bm < 4; ++bm)
#pragma unroll
                for (int bn = 0; bn < NBN; ++bn) MMA_FP16(acc[bm][bn], ah[bm], bh[bn]);
            if (PROJ) {
                uint32_t al[4][4];
#pragma unroll
                for (int bm = 0; bm < 4; ++bm)
                    LDSM4(al[bm][0], al[bm][1], al[bm][2], al[bm][3], sAl + rA[bm] + cz);
#pragma unroll
                for (int bm = 0; bm < 4; ++bm)
#pragma unroll
                    for (int bn = 0; bn < NBN; ++bn) MMA_FP16(acc[bm][bn], al[bm], bh[bn]);
            }
        }
        if (++st == NSTAGE) st = 0;
        if (i + 1 < nch) __syncthreads();
    }
#undef LOAD_CHUNK
#undef LOAD_TILE

    const int g4 = lane >> 2, t4 = lane & 3;

    if (MODE == 3) {
        // ---- fused residual + LayerNorm (BN == 256 covers the full row) ----
        __syncthreads();
        float2* part = reinterpret_cast<float2*>(smem);          // [128][16]
        float*  musg = reinterpret_cast<float*>(smem + 16384);   // [128][2]
        const int slice = wn * 4 + t4;

        float psum[8], psq[8];
#pragma unroll
        for (int r8 = 0; r8 < 8; ++r8) { psum[r8] = 0.f; psq[r8] = 0.f; }
#pragma unroll
        for (int bm = 0; bm < 4; ++bm)
#pragma unroll
            for (int half = 0; half < 2; ++half) {
                const int gr = mBase + wm * 64 + bm * 16 + g4 + half * 8;
                const int r8 = bm * 2 + half;
#pragma unroll
                for (int bn = 0; bn < NBN; ++bn) {
                    const int c0 = wn * WNT + bn * 8 + t4 * 2;
                    float2 rx = *reinterpret_cast<const float2*>(
                        resid + (size_t)gr * DIM + c0);
                    float v0 = acc[bm][bn][half * 2 + 0] + rx.x;
                    float v1 = acc[bm][bn][half * 2 + 1] + rx.y;
                    psum[r8] += v0 + v1;
                    psq[r8]  += v0 * v0 + v1 * v1;
                }
            }
#pragma unroll
        for (int bm = 0; bm < 4; ++bm)
#pragma unroll
            for (int half = 0; half < 2; ++half) {
                const int lr = wm * 64 + bm * 16 + g4 + half * 8;
                const int r8 = bm * 2 + half;
                float2 p; p.x = psum[r8]; p.y = psq[r8];
                part[lr * 16 + slice] = p;
            }
        __syncthreads();
        if (tid < 128) {
            float s = 0.f, q = 0.f;
#pragma unroll
            for (int k = 0; k < 16; ++k) {
                float2 p = part[tid * 16 + k];
                s += p.x; q += p.y;
            }
            float mu  = s * (1.0f / 256.0f);
            float var = q * (1.0f / 256.0f) - mu * mu;
            musg[tid * 2]     = mu;
            musg[tid * 2 + 1] = rsqrtf(var + 1e-5f);
        }
        __syncthreads();
#pragma unroll
        for (int bm = 0; bm < 4; ++bm)
#pragma unroll
            for (int half = 0; half < 2; ++half) {
                const int lr = wm * 64 + bm * 16 + g4 + half * 8;
                const int gr = mBase + lr;
                const float mu  = musg[lr * 2];
                const float inv = musg[lr * 2 + 1];
#pragma unroll
                for (int bn = 0; bn < NBN; ++bn) {
                    const int c0 = wn * WNT + bn * 8 + t4 * 2;
                    size_t off = (size_t)gr * DIM + c0;
                    float2 rx = *reinterpret_cast<const float2*>(resid + off);
                    float v0 = acc[bm][bn][half * 2 + 0] + rx.x;
                    float v1 = acc[bm][bn][half * 2 + 1] + rx.y;
                    float2 gb0 = *reinterpret_cast<const float2*>(gamma + c0);
                    float2 bb0 = *reinterpret_cast<const float2*>(beta + c0);
                    float2 o;
                    o.x = (v0 - mu) * inv * gb0.x + bb0.x;
                    o.y = (v1 - mu) * inv * gb0.y + bb0.y;
                    *reinterpret_cast<float2*>(ep_f + off) = o;
                }
            }
        return;
    }

    // MODE 4: permuted fp16 single store
#pragma unroll
    for (int bm = 0; bm < 4; ++bm) {
#pragma unroll
        for (int bn = 0; bn < NBN; ++bn) {
            const int r0 = mBase + wm * 64 + bm * 16 + g4;
            const int c0 = nBase + wn * WNT + bn * 8 + t4 * 2;
            const float* a4 = acc[bm][bn];
#pragma unroll
            for (int half = 0; half < 2; ++half) {
                const int gr = r0 + half * 8;
                const int bb = gr >> 11, rr = gr & 2047;
                const int hh = rr >> 9, ib = (rr & 511) << 2;
                const int ii = ib | (c0 >> 8), dd = c0 & 255;
                size_t base = (size_t)z * strideEz +
                              ((size_t)(bb * 4 + hh) * SEQ + ii) * DIM + dd;
                *reinterpret_cast<__half2*>((__half*)ep_a + base) =
                    __floats2half2_rn(a4[half * 2 + 0], a4[half * 2 + 1]);
            }
        }
    }
}

// ============ 512-thread GEMM (scores MODE 1 / pv MODE 2): BM=128, BN=256 ============
// 4x4 warp grid, warp tile 32x64, Kc=64, 3 stages x 48KB, 1 CTA/SM (16 warps)
template<int MODE>
__global__ void __launch_bounds__(512, 1)
k_mma512(const uint8_t* __restrict__ Ah, const uint8_t* __restrict__ Bh,
         int lda, int ldb, int K,
         size_t strideAz, size_t strideBz, int bShift,
         float* __restrict__ ep_f, void* __restrict__ ep_a, size_t strideEz)
{
    constexpr int STAGE  = 49152;   // A 16KB + B 32KB
    constexpr int NSTAGE = 3;
    extern __shared__ __align__(1024) char smem[];
    const uint32_t sb = smem_u32(smem);
    const int tid = threadIdx.x;
    const int wid = tid >> 5, lane = tid & 31;
    const int wm = wid >> 2, wn = wid & 3;          // 4 x 4 warp grid
    const int mBase = blockIdx.y * 128, nBase = blockIdx.x * 256;
    const int z = blockIdx.z;

    const uint8_t* A0 = Ah + (size_t)z * strideAz * 2;
    const uint8_t* B0 = Bh + (size_t)(z >> bShift) * strideBz * 2;

    const int nch = K >> 6;

#define LOAD_TILE5(srcB, ldE, rowB, k0, dstOff, ROWS)                                 \
    { _Pragma("unroll") for (int p_ = 0; p_ < (ROWS) / 64; ++p_) {                    \
        int idx_ = tid + 512 * p_;                                                    \
        int row_ = idx_ >> 3, c16_ = idx_ & 7;                                        \
        const uint8_t* g_ = (srcB) +                                                  \
            ((size_t)((rowB) + row_) * (ldE) + (k0) + c16_ * 8) * 2;                  \
        uint32_t d_ = sb + (dstOff) + row_ * 128 +                                    \
                      ((c16_ * 16) ^ ((row_ & 7) << 4));                              \
        CP16(d_, g_); } }

#define LOAD_CHUNK5(i_, s_)                                                           \
    {                                                                                 \
        const int k0_ = (i_) * 64;                                                    \
        const int so_ = (s_) * STAGE;                                                 \
        LOAD_TILE5(A0, lda, mBase, k0_, so_, 128);                                    \
        LOAD_TILE5(B0, ldb, nBase, k0_, so_ + 16384, 256);                            \
        CP_COMMIT();                                                                  \
    }

    const int lrow = (lane & 7) + ((lane >> 3) & 1) * 8;
    const int kh16 = ((lane >> 4) & 1) * 16;
    const int swz  = (lane & 7) << 4;
    int rA[2], rB[4];
#pragma unroll
    for (int bm = 0; bm < 2; ++bm) rA[bm] = (wm * 32 + bm * 16 + lrow) * 128;
#pragma unroll
    for (int nb = 0; nb < 4; ++nb) rB[nb] = (wn * 64 + nb * 16 + lrow) * 128;

    float acc[2][8][4];
#pragma unroll
    for (int a = 0; a < 2; ++a)
#pragma unroll
        for (int b = 0; b < 8; ++b)
#pragma unroll
            for (int c = 0; c < 4; ++c) acc[a][b][c] = 0.f;

#pragma unroll
    for (int p = 0; p < NSTAGE - 1; ++p)
        if (p < nch) LOAD_CHUNK5(p, p);

    int st = 0;
    for (int i = 0; i < nch; ++i) {
        const int rem = nch - 1 - i;
        if (rem >= 1) { CP_WAIT1(); } else { CP_WAIT0(); }
        __syncthreads();
        if (i + NSTAGE - 1 < nch) {
            int s2 = st + NSTAGE - 1; if (s2 >= NSTAGE) s2 -= NSTAGE;
            LOAD_CHUNK5(i + NSTAGE - 1, s2);
        }

        const uint32_t sA = sb + st * STAGE;
        const uint32_t sB = sA + 16384;

#pragma unroll
        for (int ks = 0; ks < 4; ++ks) {
            const int cz = ((ks * 32) + kh16) ^ swz;
            uint32_t ah[2][4];
#pragma unroll
            for (int bm = 0; bm < 2; ++bm)
                LDSM4(ah[bm][0], ah[bm][1], ah[bm][2], ah[bm][3], sA + rA[bm] + cz);
            uint32_t bh[8][2];
#pragma unroll
            for (int nb = 0; nb < 4; ++nb) {
                uint32_t t0, t1, t2, t3;
                LDSM4(t0, t1, t2, t3, sB + rB[nb] + cz);
                bh[nb * 2][0] = t0; bh[nb * 2][1] = t2;
                bh[nb * 2 + 1][0] = t1; bh[nb * 2 + 1][1] = t3;
            }
#pragma unroll
            for (int bm = 0; bm < 2; ++bm)
#pragma unroll
                for (int bn = 0; bn < 8; ++bn) MMA_FP16(acc[bm][bn], ah[bm], bh[bn]);
        }
        if (++st == NSTAGE) st = 0;
        if (i + 1 < nch) __syncthreads();
    }
#undef LOAD_CHUNK5
#undef LOAD_TILE5

    // epilogue
    const int g4 = lane >> 2, t4 = lane & 3;
#pragma unroll
    for (int bm = 0; bm < 2; ++bm) {
#pragma unroll
        for (int bn = 0; bn < 8; ++bn) {
            const int r0 = mBase + wm * 32 + bm * 16 + g4;
            const int c0 = nBase + wn * 64 + bn * 8 + t4 * 2;
            const float* a4 = acc[bm][bn];
#pragma unroll
            for (int half = 0; half < 2; ++half) {
                const int gr = r0 + half * 8;
                const float v0 = a4[half * 2 + 0];
                const float v1 = a4[half * 2 + 1];
                if (MODE == 1) {
                    float2 q; q.x = v0 * 0.0625f; q.y = v1 * 0.0625f;
                    *reinterpret_cast<float2*>(
                        ep_f + (size_t)z * strideEz + (size_t)gr * SEQ + c0) = q;
                } else {  // MODE 2: fp16 single att
                    const int bb = z >> 2, h = z & 3;
                    size_t base = ((size_t)(bb * SEQ + gr)) * HD + h * DIM + c0;
                    *reinterpret_cast<__half2*>((__half*)ep_a + base) =
                        __floats2half2_rn(v0, v1);
                }
            }
        }
    }
}

// ======================= softmax (max-free) =======================
__global__ void k_softmax(float* __restrict__ probs, __half* __restrict__ pf)
{
    const size_t row = blockIdx.x;
    float4* p4 = reinterpret_cast<float4*>(probs + row * SEQ);
    const int t = threadIdx.x;
    const int wid = t >> 5, lane = t & 31;
    __shared__ float red[8];

    float4 v[2];
    v[0] = p4[t]; v[1] = p4[t + 256];

    float sum = 0.f;
#pragma unroll
    for (int q = 0; q < 2; ++q) {
        v[q].x = __expf(v[q].x); v[q].y = __expf(v[q].y);
        v[q].z = __expf(v[q].z); v[q].w = __expf(v[q].w);
        sum += v[q].x + v[q].y + v[q].z + v[q].w;
    }
#pragma unroll
    for (int s = 16; s > 0; s >>= 1) sum += __shfl_xor_sync(~0u, sum, s);
    if (lane == 0) red[wid] = sum;
    __syncthreads();
    float s0 = red[lane & 7];
#pragma unroll
    for (int s = 4; s > 0; s >>= 1) s0 += __shfl_xor_sync(~0u, s0, s);
    const float inv = 1.0f / __shfl_sync(~0u, s0, 0);

#pragma unroll
    for (int q = 0; q < 2; ++q) {
        v[q].x *= inv; v[q].y *= inv; v[q].z *= inv; v[q].w *= inv;
    }
    p4[t] = v[0]; p4[t + 256] = v[1];

    __half2* pf2 = reinterpret_cast<__half2*>(pf + row * SEQ);
    pf2[2 * t]             = __floats2half2_rn(v[0].x, v[0].y);
    pf2[2 * t + 1]         = __floats2half2_rn(v[0].z, v[0].w);
    pf2[2 * (t + 256)]     = __floats2half2_rn(v[1].x, v[1].y);
    pf2[2 * (t + 256) + 1] = __floats2half2_rn(v[1].z, v[1].w);
}

// ======================= launch =======================
extern "C" void kernel_launch(void* const* d_in, const int* in_sizes, int n_in,
                              void* d_out, int out_size)
{
    const float* x     = (const float*)d_in[0];
    const float* Wq    = (const float*)d_in[1];
    const float* Wk    = (const float*)d_in[2];
    const float* Wv    = (const float*)d_in[3];
    const float* gamma = (const float*)d_in[4];
    const float* beta  = (const float*)d_in[5];

    __half *xhf, *xlf, *xTf, *wqktf, *wvtf, *QKf, *Pf, *attf;
    float *outFb, *probsFb;
    cudaGetSymbolAddress((void**)&xhf, g_xhf);     cudaGetSymbolAddress((void**)&xlf, g_xlf);
    cudaGetSymbolAddress((void**)&xTf, g_xTf);
    cudaGetSymbolAddress((void**)&wqktf, g_wqktf); cudaGetSymbolAddress((void**)&wvtf, g_wvtf);
    cudaGetSymbolAddress((void**)&QKf, g_QKf);
    cudaGetSymbolAddress((void**)&Pf, g_Pf);
    cudaGetSymbolAddress((void**)&attf, g_attf);
    cudaGetSymbolAddress((void**)&outFb, g_out_fb);
    cudaGetSymbolAddress((void**)&probsFb, g_probs_fb);

    const long long OUT_E = (long long)BS * SEQ * DIM;
    const long long PR_E  = (long long)BHN * SEQ * SEQ;
    long long osz = out_size;
    float *outp, *probs;
    if (osz >= OUT_E + PR_E) { outp = (float*)d_out; probs = (float*)d_out + OUT_E; }
    else if (osz >= PR_E)    { probs = (float*)d_out; outp = outFb; }
    else                     { outp = (float*)d_out; probs = probsFb; }

    cudaFuncSetAttribute((const void*)k_mma<4, 128>, cudaFuncAttributeMaxDynamicSharedMemorySize, 98304);
    cudaFuncSetAttribute((const void*)k_mma<3, 256>, cudaFuncAttributeMaxDynamicSharedMemorySize, 98304);
    cudaFuncSetAttribute((const void*)k_mma512<1>, cudaFuncAttributeMaxDynamicSharedMemorySize, 147456);
    cudaFuncSetAttribute((const void*)k_mma512<2>, cudaFuncAttributeMaxDynamicSharedMemorySize, 147456);

    const size_t QK_Z = (size_t)BHN * SEQ * DIM;

    // 1: fused prep
    k_prep<<<3840, 256>>>(x, Wq, Wk, Wv, xhf, xlf, xTf, wqktf, wvtf);

    // 2: Q+K projections merged (z=0 -> Qf, z=1 -> Kf), fp16 2-product
    k_mma<4, 128><<<dim3(8, 64, 2), 256, 98304>>>((const uint8_t*)xhf, (const uint8_t*)xlf,
        (const uint8_t*)wqktf, 256, 256, 256,
        0, (size_t)HD * DIM, 0, nullptr, QKf, nullptr, nullptr, nullptr, QK_Z);

    // 3: scores (per bh: 2048x2048, K=256), 512-thread BM128xBN256
    k_mma512<1><<<dim3(8, 16, BHN), 512, 147456>>>((const uint8_t*)QKf,
        (const uint8_t*)(QKf + QK_Z), 256, 256, 256,
        (size_t)SEQ * DIM, (size_t)SEQ * DIM, 0,
        probs, nullptr, (size_t)SEQ * SEQ);

    // 4: softmax (max-free, fp32 + fp16 copy)
    k_softmax<<<BHN * SEQ, 256>>>(probs, Pf);

    // 5: PV (per bh: 2048x256, K=2048), 512-thread BM128xBN256 (full N, Pf read once)
    k_mma512<2><<<dim3(1, 16, BHN), 512, 147456>>>((const uint8_t*)Pf,
        (const uint8_t*)xTf, 2048, 2048, 2048,
        (size_t)SEQ * SEQ, (size_t)DIM * SEQ, 2,
        nullptr, attf, 0);

    // 6: att @ Wv + x -> LayerNorm -> out, fused epilogue
    k_mma<3, 256><<<dim3(1, 64, 1), 256, 98304>>>((const uint8_t*)attf, nullptr,
        (const uint8_t*)wvtf, 1024, 1024, 1024,
        0, 0, 0, outp, nullptr, x, gamma, beta, 0);
}

// round 14
// speedup vs baseline: 1.0895x; 1.0895x over previous
#include <cuda_runtime.h>
#include <cuda_bf16.h>
#include <cuda_fp16.h>
#include <cstdint>
#include <cstddef>

#define BS   4
#define SEQ  2048
#define DIM  256
#define HH   4
#define HD   1024
#define BHN  16

// ======================= device scratch =======================
__device__ __align__(256) __half g_xhf [(size_t)BS*SEQ*DIM];      // x fp16 split hi
__device__ __align__(256) __half g_xlf [(size_t)BS*SEQ*DIM];      // x fp16 split lo
__device__ __align__(256) __half g_xTf [(size_t)BS*DIM*SEQ];      // x^T fp16 single
__device__ __align__(256) __half g_wqktf[(size_t)2*HD*DIM];       // Wq^T | Wk^T fp16
__device__ __align__(256) __half g_wvtf[(size_t)DIM*HD];          // Wv^T fp16 single
__device__ __align__(256) __half g_QKf [(size_t)2*BHN*SEQ*DIM];   // Qf | Kf (fp16)
__device__ __align__(256) __half g_Ef  [(size_t)BHN*SEQ*SEQ];     // fp16 exp(scores)
__device__ __align__(256) float  g_part[(size_t)BHN*16*SEQ];      // per-jtile row partials
__device__ __align__(256) float  g_inv [(size_t)BHN*SEQ];         // 1/rowsum
__device__ __align__(256) __half g_attf[(size_t)BS*SEQ*HD];       // att fp16 single
__device__ __align__(256) float  g_out_fb [(size_t)BS*SEQ*DIM];
__device__ __align__(256) float  g_probs_fb[(size_t)BHN*SEQ*SEQ];

// ======================= helpers =======================
__device__ __forceinline__ uint32_t smem_u32(const void* p) {
    uint32_t a;
    asm("{ .reg .u64 t; cvta.to.shared.u64 t, %1; cvt.u32.u64 %0, t; }" : "=r"(a) : "l"(p));
    return a;
}
#define CP16(dst, src) \
    asm volatile("cp.async.cg.shared.global [%0], [%1], 16;" :: "r"(dst), "l"(src))
#define CP_COMMIT() asm volatile("cp.async.commit_group;" ::: "memory")
#define CP_WAIT0()  asm volatile("cp.async.wait_group 0;" ::: "memory")
#define CP_WAIT1()  asm volatile("cp.async.wait_group 1;" ::: "memory")

#define LDSM4(r0, r1, r2, r3, a) \
    asm volatile("ldmatrix.sync.aligned.m8n8.x4.shared.b16 {%0,%1,%2,%3}, [%4];" \
        : "=r"(r0), "=r"(r1), "=r"(r2), "=r"(r3) : "r"(a))

#define MMA_FP16(d, a, b) \
    asm volatile("mma.sync.aligned.m16n8k16.row.col.f32.f16.f16.f32 " \
        "{%0,%1,%2,%3}, {%4,%5,%6,%7}, {%8,%9}, {%0,%1,%2,%3};" \
        : "+f"((d)[0]), "+f"((d)[1]), "+f"((d)[2]), "+f"((d)[3]) \
        : "r"((a)[0]), "r"((a)[1]), "r"((a)[2]), "r"((a)[3]), \
          "r"((b)[0]), "r"((b)[1]))

// ======================= fused prep kernel =======================
__global__ void k_prep(const float* __restrict__ x, const float* __restrict__ Wq,
                       const float* __restrict__ Wk, const float* __restrict__ Wv,
                       __half* __restrict__ xhf, __half* __restrict__ xlf,
                       __half* __restrict__ xTf,
                       __half* __restrict__ wqktf, __half* __restrict__ wvtf)
{
    int b = blockIdx.x;
    const int tid = threadIdx.x;
    if (b < 1024) {
        int i0 = b * 2048 + tid;
#pragma unroll
        for (int q = 0; q < 8; ++q) {
            int i = i0 + q * 256;
            float v = x[i];
            __half h = __float2half_rn(v);
            __half l = __float2half_rn(v - __half2float(h));
            xhf[i] = h; xlf[i] = l;
        }
        return;
    }
    b -= 1024;
    const float* in; int R, C, bx, by;
    __half* oh;
    if (b < 256)      { in = Wq; oh = wqktf; R = 256;  C = 1024; bx = b & 31; by = b >> 5; }
    else if (b < 512) { b -= 256; in = Wk; oh = wqktf + (size_t)HD * DIM;
                        R = 256; C = 1024; bx = b & 31; by = b >> 5; }
    else if (b < 768) { b -= 512; in = Wv; oh = wvtf; R = 1024; C = 256; bx = b & 7; by = b >> 3; }
    else {
        b -= 768;
        int z = b >> 9, t = b & 511;
        in = x + (size_t)z * SEQ * DIM;
        oh = xTf + (size_t)z * DIM * SEQ;
        R = 2048; C = 256; bx = t & 7; by = t >> 3;
    }

    __shared__ float tbuf[32][33];
    const int tx = tid & 31, ty = tid >> 5;
    const int c0 = bx * 32, r0 = by * 32;
#pragma unroll
    for (int i = 0; i < 4; ++i)
        tbuf[ty + i * 8][tx] = in[(size_t)(r0 + ty + i * 8) * C + c0 + tx];
    __syncthreads();
#pragma unroll
    for (int i = 0; i < 4; ++i) {
        float v = tbuf[tx][ty + i * 8];
        oh[(size_t)(c0 + ty + i * 8) * R + r0 + tx] = __float2half_rn(v);
    }
}

// ======================= warp-MMA GEMM, cp.async pipeline, Kc=64 ====================
// MODE 4: proj Q+K (fp16 A-split 2-product, 3 tiles, 2-stage, BN=128, 2 CTA/SM)
// MODE 1: scores  (fp16 1-product, 3-stage, BN=128) -> fp16 exp(s/16) + row partials
// MODE 2: pv      (fp16 1-product, 3-stage, BN=128) -> fp16 att, rows scaled by inv
// MODE 3: wv      (fp16 1-product, 2-stage, BN=256) -> residual + fused LayerNorm
template<int MODE, int BN>
__global__ void __launch_bounds__(256, (BN == 256) ? 1 : 2)
k_mma(const uint8_t* __restrict__ Ah, const uint8_t* __restrict__ Al,
      const uint8_t* __restrict__ Bh,
      int lda, int ldb, int K,
      size_t strideAz, size_t strideBz, int bShift,
      float* __restrict__ ep_f, void* __restrict__ ep_a,
      const float* __restrict__ resid,
      const float* __restrict__ gamma, const float* __restrict__ beta,
      size_t strideEz)
{
    constexpr bool PROJ   = (MODE == 4);
    constexpr int  WNT    = BN / 4;
    constexpr int  NBN    = BN / 32;
    constexpr int  NBL    = BN / 64;
    constexpr int  STAGE  = PROJ ? 49152 : (16384 + BN * 128);
    constexpr int  NSTAGE = (!PROJ && BN == 128) ? 3 : 2;
    extern __shared__ __align__(1024) char smem[];
    const uint32_t sb = smem_u32(smem);
    const int tid = threadIdx.x;
    const int wid = tid >> 5, lane = tid & 31;
    const int wm = wid >> 2, wn = wid & 3;
    const int mBase = blockIdx.y * 128, nBase = blockIdx.x * BN;
    const int z = blockIdx.z;

    const uint8_t* A0 = Ah + (size_t)z * strideAz * 2;
    const uint8_t* A1 = PROJ ? Al + (size_t)z * strideAz * 2 : nullptr;
    const uint8_t* B0 = Bh + (size_t)(z >> bShift) * strideBz * 2;

    const int nch = K >> 6;

#define LOAD_TILE(srcB, ldE, rowB, k0, dstOff, ROWS)                                  \
    { _Pragma("unroll") for (int p_ = 0; p_ < (ROWS) / 32; ++p_) {                    \
        int idx_ = tid + 256 * p_;                                                    \
        int row_ = idx_ >> 3, c16_ = idx_ & 7;                                        \
        const uint8_t* g_ = (srcB) +                                                  \
            ((size_t)((rowB) + row_) * (ldE) + (k0) + c16_ * 8) * 2;                  \
        uint32_t d_ = sb + (dstOff) + row_ * 128 +                                    \
                      ((c16_ * 16) ^ ((row_ & 7) << 4));                              \
        CP16(d_, g_); } }

#define LOAD_CHUNK(i_, s_)                                                            \
    {                                                                                 \
        const int k0_ = (i_) * 64;                                                    \
        const int so_ = (s_) * STAGE;                                                 \
        if (PROJ) {                                                                   \
            LOAD_TILE(A0, lda, mBase, k0_, so_, 128);                                 \
            LOAD_TILE(A1, lda, mBase, k0_, so_ + 16384, 128);                         \
            LOAD_TILE(B0, ldb, nBase, k0_, so_ + 32768, 128);                         \
        } else {                                                                      \
            LOAD_TILE(A0, lda, mBase, k0_, so_, 128);                                 \
            LOAD_TILE(B0, ldb, nBase, k0_, so_ + 16384, BN);                          \
        }                                                                             \
        CP_COMMIT();                                                                  \
    }

    const int lrow = (lane & 7) + ((lane >> 3) & 1) * 8;
    const int kh16 = ((lane >> 4) & 1) * 16;
    const int swz  = (lane & 7) << 4;
    int rA[4], rB[NBL];
#pragma unroll
    for (int bm = 0; bm < 4; ++bm) rA[bm] = (wm * 64 + bm * 16 + lrow) * 128;
#pragma unroll
    for (int nb = 0; nb < NBL; ++nb) rB[nb] = (wn * WNT + nb * 16 + lrow) * 128;

    float acc[4][NBN][4];
#pragma unroll
    for (int a = 0; a < 4; ++a)
#pragma unroll
        for (int b = 0; b < NBN; ++b)
#pragma unroll
            for (int c = 0; c < 4; ++c) acc[a][b][c] = 0.f;

#pragma unroll
    for (int p = 0; p < NSTAGE - 1; ++p)
        if (p < nch) LOAD_CHUNK(p, p);

    int st = 0;
    for (int i = 0; i < nch; ++i) {
        const int rem = nch - 1 - i;
        if (NSTAGE == 3) {
            if (rem >= 1) { CP_WAIT1(); } else { CP_WAIT0(); }
        } else {
            CP_WAIT0();
        }
        __syncthreads();
        if (i + NSTAGE - 1 < nch) {
            int s2 = st + NSTAGE - 1; if (s2 >= NSTAGE) s2 -= NSTAGE;
            LOAD_CHUNK(i + NSTAGE - 1, s2);
        }

        const uint32_t so = sb + st * STAGE;
        const uint32_t sA  = so;
        const uint32_t sAl = so + 16384;
        const uint32_t sB  = so + (PROJ ? 32768 : 16384);

#pragma unroll
        for (int ks = 0; ks < 4; ++ks) {
            const int cz = ((ks * 32) + kh16) ^ swz;
            uint32_t ah[4][4];
#pragma unroll
            for (int bm = 0; bm < 4; ++bm)
                LDSM4(ah[bm][0], ah[bm][1], ah[bm][2], ah[bm][3], sA + rA[bm] + cz);
            uint32_t bh[NBN][2];
#pragma unroll
            for (int nb = 0; nb < NBL; ++nb) {
                uint32_t t0, t1, t2, t3;
                LDSM4(t0, t1, t2, t3, sB + rB[nb] + cz);
                bh[nb * 2][0] = t0; bh[nb * 2][1] = t2;
                bh[nb * 2 + 1][0] = t1; bh[nb * 2 + 1][1] = t3;
            }
#pragma unroll
            for (int bm = 0; bm < 4; ++bm)
#pragma unroll
                for (int bn = 0; bn < NBN; ++bn) MMA_FP16(acc[bm][bn], ah[bm], bh[bn]);
            if (PROJ) {
                uint32_t al[4][4];
#pragma unroll
                for (int bm = 0; bm < 4; ++bm)
                    LDSM4(al[bm][0], al[bm][1], al[bm][2], al[bm][3], sAl + rA[bm] + cz);
#pragma unroll
                for (int bm = 0; bm < 4; ++bm)
#pragma unroll
                    for (int bn = 0; bn < NBN; ++bn) MMA_FP16(acc[bm][bn], al[bm], bh[bn]);
            }
        }
        if (++st == NSTAGE) st = 0;
        if (i + 1 < nch) __syncthreads();
    }
#undef LOAD_CHUNK
#undef LOAD_TILE

    // ======================= epilogue =======================
    const int g4 = lane >> 2, t4 = lane & 3;

    if (MODE == 1) {
        // exp(s/16) -> fp16 Ef + deterministic per-CTA row partial sums
        __syncthreads();
        float* rowp = reinterpret_cast<float*>(smem);   // [128][4]
        float rp[8];
#pragma unroll
        for (int r8 = 0; r8 < 8; ++r8) rp[r8] = 0.f;
#pragma unroll
        for (int bm = 0; bm < 4; ++bm)
#pragma unroll
            for (int half = 0; half < 2; ++half) {
                const int gr = mBase + wm * 64 + bm * 16 + g4 + half * 8;
                const int r8 = bm * 2 + half;
#pragma unroll
                for (int bn = 0; bn < NBN; ++bn) {
                    const int c0 = nBase + wn * WNT + bn * 8 + t4 * 2;
                    float e0 = __expf(acc[bm][bn][half * 2 + 0] * 0.0625f);
                    float e1 = __expf(acc[bm][bn][half * 2 + 1] * 0.0625f);
                    *reinterpret_cast<__half2*>((__half*)ep_a +
                        (size_t)z * strideEz + (size_t)gr * SEQ + c0) =
                        __floats2half2_rn(e0, e1);
                    rp[r8] += e0 + e1;
                }
            }
#pragma unroll
        for (int r8 = 0; r8 < 8; ++r8) {
            rp[r8] += __shfl_xor_sync(~0u, rp[r8], 1);
            rp[r8] += __shfl_xor_sync(~0u, rp[r8], 2);
        }
        if (t4 == 0) {
#pragma unroll
            for (int bm = 0; bm < 4; ++bm)
#pragma unroll
                for (int half = 0; half < 2; ++half) {
                    const int lr = wm * 64 + bm * 16 + g4 + half * 8;
                    rowp[lr * 4 + wn] = rp[bm * 2 + half];
                }
        }
        __syncthreads();
        if (tid < 128) {
            float s = rowp[tid * 4] + rowp[tid * 4 + 1]
                    + rowp[tid * 4 + 2] + rowp[tid * 4 + 3];
            ep_f[((size_t)z * 16 + blockIdx.x) * SEQ + mBase + tid] = s;
        }
        return;
    }

    if (MODE == 3) {
        // ---- fused residual + LayerNorm (BN == 256 covers the full row) ----
        __syncthreads();
        float2* part = reinterpret_cast<float2*>(smem);          // [128][16]
        float*  musg = reinterpret_cast<float*>(smem + 16384);   // [128][2]
        const int slice = wn * 4 + t4;

        float psum[8], psq[8];
#pragma unroll
        for (int r8 = 0; r8 < 8; ++r8) { psum[r8] = 0.f; psq[r8] = 0.f; }
#pragma unroll
        for (int bm = 0; bm < 4; ++bm)
#pragma unroll
            for (int half = 0; half < 2; ++half) {
                const int gr = mBase + wm * 64 + bm * 16 + g4 + half * 8;
                const int r8 = bm * 2 + half;
#pragma unroll
                for (int bn = 0; bn < NBN; ++bn) {
                    const int c0 = wn * WNT + bn * 8 + t4 * 2;
                    float2 rx = *reinterpret_cast<const float2*>(
                        resid + (size_t)gr * DIM + c0);
                    float v0 = acc[bm][bn][half * 2 + 0] + rx.x;
                    float v1 = acc[bm][bn][half * 2 + 1] + rx.y;
                    psum[r8] += v0 + v1;
                    psq[r8]  += v0 * v0 + v1 * v1;
                }
            }
#pragma unroll
        for (int bm = 0; bm < 4; ++bm)
#pragma unroll
            for (int half = 0; half < 2; ++half) {
                const int lr = wm * 64 + bm * 16 + g4 + half * 8;
                const int r8 = bm * 2 + half;
                float2 p; p.x = psum[r8]; p.y = psq[r8];
                part[lr * 16 + slice] = p;
            }
        __syncthreads();
        if (tid < 128) {
            float s = 0.f, q = 0.f;
#pragma unroll
            for (int k = 0; k < 16; ++k) {
                float2 p = part[tid * 16 + k];
                s += p.x; q += p.y;
            }
            float mu  = s * (1.0f / 256.0f);
            float var = q * (1.0f / 256.0f) - mu * mu;
            musg[tid * 2]     = mu;
            musg[tid * 2 + 1] = rsqrtf(var + 1e-5f);
        }
        __syncthreads();
#pragma unroll
        for (int bm = 0; bm < 4; ++bm)
#pragma unroll
            for (int half = 0; half < 2; ++half) {
                const int lr = wm * 64 + bm * 16 + g4 + half * 8;
                const int gr = mBase + lr;
                const float mu  = musg[lr * 2];
                const float inv = musg[lr * 2 + 1];
#pragma unroll
                for (int bn = 0; bn < NBN; ++bn) {
                    const int c0 = wn * WNT + bn * 8 + t4 * 2;
                    size_t off = (size_t)gr * DIM + c0;
                    float2 rx = *reinterpret_cast<const float2*>(resid + off);
                    float v0 = acc[bm][bn][half * 2 + 0] + rx.x;
                    float v1 = acc[bm][bn][half * 2 + 1] + rx.y;
                    float2 gb0 = *reinterpret_cast<const float2*>(gamma + c0);
                    float2 bb0 = *reinterpret_cast<const float2*>(beta + c0);
                    float2 o;
                    o.x = (v0 - mu) * inv * gb0.x + bb0.x;
                    o.y = (v1 - mu) * inv * gb0.y + bb0.y;
                    *reinterpret_cast<float2*>(ep_f + off) = o;
                }
            }
        return;
    }

#pragma unroll
    for (int bm = 0; bm < 4; ++bm) {
#pragma unroll
        for (int bn = 0; bn < NBN; ++bn) {
            const int r0 = mBase + wm * 64 + bm * 16 + g4;
            const int c0 = nBase + wn * WNT + bn * 8 + t4 * 2;
            const float* a4 = acc[bm][bn];
#pragma unroll
            for (int half = 0; half < 2; ++half) {
                const int gr = r0 + half * 8;
                const float v0 = a4[half * 2 + 0];
                const float v1 = a4[half * 2 + 1];
                if (MODE == 4) {
                    const int bb = gr >> 11, rr = gr & 2047;
                    const int hh = rr >> 9, ib = (rr & 511) << 2;
                    const int ii = ib | (c0 >> 8), dd = c0 & 255;
                    size_t base = (size_t)z * strideEz +
                                  ((size_t)(bb * 4 + hh) * SEQ + ii) * DIM + dd;
                    *reinterpret_cast<__half2*>((__half*)ep_a + base) =
                        __floats2half2_rn(v0, v1);
                } else {  // MODE 2: att scaled by row inv
                    const float sc = resid[(size_t)z * SEQ + gr];
                    const int bb = z >> 2, h = z & 3;
                    size_t base = ((size_t)(bb * SEQ + gr)) * HD + h * DIM + c0;
                    *reinterpret_cast<__half2*>((__half*)ep_a + base) =
                        __floats2half2_rn(v0 * sc, v1 * sc);
                }
            }
        }
    }
}

// ======================= rowsum inverse =======================
__global__ void k_rowinv(const float* __restrict__ part, float* __restrict__ inv)
{
    const int gid = blockIdx.x * 256 + threadIdx.x;   // 32768 rows
    const int z = gid >> 11, i = gid & 2047;
    const float* p = part + (size_t)z * 16 * SEQ + i;
    float s = 0.f;
#pragma unroll
    for (int jt = 0; jt < 16; ++jt) s += p[(size_t)jt * SEQ];
    inv[gid] = 1.0f / s;
}

// ======================= normalize: probs = Ef * inv =======================
__global__ void k_norm(const __half* __restrict__ Ef, const float* __restrict__ inv,
                       float* __restrict__ probs)
{
    const size_t row = blockIdx.x;
    const float iv = inv[row];
    const int t = threadIdx.x;    // 256 threads x 8 halves
    uint4 u = reinterpret_cast<const uint4*>(Ef + row * SEQ)[t];
    float2 f0 = __half22float2(*reinterpret_cast<__half2*>(&u.x));
    float2 f1 = __half22float2(*reinterpret_cast<__half2*>(&u.y));
    float2 f2 = __half22float2(*reinterpret_cast<__half2*>(&u.z));
    float2 f3 = __half22float2(*reinterpret_cast<__half2*>(&u.w));
    float4 o0, o1;
    o0.x = f0.x * iv; o0.y = f0.y * iv; o0.z = f1.x * iv; o0.w = f1.y * iv;
    o1.x = f2.x * iv; o1.y = f2.y * iv; o1.z = f3.x * iv; o1.w = f3.y * iv;
    float4* p4 = reinterpret_cast<float4*>(probs + row * SEQ);
    p4[2 * t]     = o0;
    p4[2 * t + 1] = o1;
}

// ======================= launch =======================
extern "C" void kernel_launch(void* const* d_in, const int* in_sizes, int n_in,
                              void* d_out, int out_size)
{
    const float* x     = (const float*)d_in[0];
    const float* Wq    = (const float*)d_in[1];
    const float* Wk    = (const float*)d_in[2];
    const float* Wv    = (const float*)d_in[3];
    const float* gamma = (const float*)d_in[4];
    const float* beta  = (const float*)d_in[5];

    __half *xhf, *xlf, *xTf, *wqktf, *wvtf, *QKf, *Ef, *attf;
    float *part, *inv, *outFb, *probsFb;
    cudaGetSymbolAddress((void**)&xhf, g_xhf);     cudaGetSymbolAddress((void**)&xlf, g_xlf);
    cudaGetSymbolAddress((void**)&xTf, g_xTf);
    cudaGetSymbolAddress((void**)&wqktf, g_wqktf); cudaGetSymbolAddress((void**)&wvtf, g_wvtf);
    cudaGetSymbolAddress((void**)&QKf, g_QKf);
    cudaGetSymbolAddress((void**)&Ef, g_Ef);
    cudaGetSymbolAddress((void**)&part, g_part);
    cudaGetSymbolAddress((void**)&inv, g_inv);
    cudaGetSymbolAddress((void**)&attf, g_attf);
    cudaGetSymbolAddress((void**)&outFb, g_out_fb);
    cudaGetSymbolAddress((void**)&probsFb, g_probs_fb);

    const long long OUT_E = (long long)BS * SEQ * DIM;
    const long long PR_E  = (long long)BHN * SEQ * SEQ;
    long long osz = out_size;
    float *outp, *probs;
    if (osz >= OUT_E + PR_E) { outp = (float*)d_out; probs = (float*)d_out + OUT_E; }
    else if (osz >= PR_E)    { probs = (float*)d_out; outp = outFb; }
    else                     { outp = (float*)d_out; probs = probsFb; }

    cudaFuncSetAttribute((const void*)k_mma<4, 128>, cudaFuncAttributeMaxDynamicSharedMemorySize, 98304);
    cudaFuncSetAttribute((const void*)k_mma<1, 128>, cudaFuncAttributeMaxDynamicSharedMemorySize, 98304);
    cudaFuncSetAttribute((const void*)k_mma<2, 128>, cudaFuncAttributeMaxDynamicSharedMemorySize, 98304);
    cudaFuncSetAttribute((const void*)k_mma<3, 256>, cudaFuncAttributeMaxDynamicSharedMemorySize, 98304);

    dim3 T(256);
    const size_t QK_Z = (size_t)BHN * SEQ * DIM;

    // 1: fused prep
    k_prep<<<3840, T>>>(x, Wq, Wk, Wv, xhf, xlf, xTf, wqktf, wvtf);

    // 2: Q+K projections merged (z=0 -> Qf, z=1 -> Kf), fp16 2-product
    k_mma<4, 128><<<dim3(8, 64, 2), T, 98304>>>((const uint8_t*)xhf, (const uint8_t*)xlf,
        (const uint8_t*)wqktf, 256, 256, 256,
        0, (size_t)HD * DIM, 0, nullptr, QKf, nullptr, nullptr, nullptr, QK_Z);

    // 3: scores -> exp fp16 (Ef) + row partial sums
    k_mma<1, 128><<<dim3(16, 16, BHN), T, 98304>>>((const uint8_t*)QKf, nullptr,
        (const uint8_t*)(QKf + QK_Z), 256, 256, 256,
        (size_t)SEQ * DIM, (size_t)SEQ * DIM, 0,
        part, Ef, nullptr, nullptr, nullptr, (size_t)SEQ * SEQ);

    // 4: inverse row sums
    k_rowinv<<<128, T>>>(part, inv);

    // 5: normalize -> fp32 probs output
    k_norm<<<BHN * SEQ, T>>>(Ef, inv, probs);

    // 6: PV reads Ef, epilogue scales rows by inv
    k_mma<2, 128><<<dim3(2, 16, BHN), T, 98304>>>((const uint8_t*)Ef, nullptr,
        (const uint8_t*)xTf, 2048, 2048, 2048,
        (size_t)SEQ * SEQ, (size_t)DIM * SEQ, 2,
        nullptr, attf, inv, nullptr, nullptr, 0);

    // 7: att @ Wv + x -> LayerNorm -> out, fused epilogue
    k_mma<3, 256><<<dim3(1, 64, 1), T, 98304>>>((const uint8_t*)attf, nullptr,
        (const uint8_t*)wvtf, 1024, 1024, 1024,
        0, 0, 0, outp, nullptr, x, gamma, beta, 0);
}

// round 15
// speedup vs baseline: 1.0951x; 1.0051x over previous
#include <cuda_runtime.h>
#include <cuda_bf16.h>
#include <cuda_fp16.h>
#include <cstdint>
#include <cstddef>

#define BS   4
#define SEQ  2048
#define DIM  256
#define HH   4
#define HD   1024
#define BHN  16

// ======================= device scratch =======================
__device__ __align__(256) __half g_xhf [(size_t)BS*SEQ*DIM];
__device__ __align__(256) __half g_xlf [(size_t)BS*SEQ*DIM];
__device__ __align__(256) __half g_xTf [(size_t)BS*DIM*SEQ];
__device__ __align__(256) __half g_wqktf[(size_t)2*HD*DIM];
__device__ __align__(256) __half g_wvtf[(size_t)DIM*HD];
__device__ __align__(256) __half g_QKf [(size_t)2*BHN*SEQ*DIM];
__device__ __align__(256) __half g_Ef  [(size_t)BHN*SEQ*SEQ];     // fp16 exp(scores)
__device__ __align__(256) float  g_part[(size_t)BHN*16*SEQ];      // per-jtile row partials
__device__ __align__(256) __half g_attf[(size_t)BS*SEQ*HD];
__device__ __align__(256) float  g_out_fb [(size_t)BS*SEQ*DIM];
__device__ __align__(256) float  g_probs_fb[(size_t)BHN*SEQ*SEQ];

// ======================= helpers =======================
__device__ __forceinline__ uint32_t smem_u32(const void* p) {
    uint32_t a;
    asm("{ .reg .u64 t; cvta.to.shared.u64 t, %1; cvt.u32.u64 %0, t; }" : "=r"(a) : "l"(p));
    return a;
}
#define CP16(dst, src) \
    asm volatile("cp.async.cg.shared.global [%0], [%1], 16;" :: "r"(dst), "l"(src))
#define CP_COMMIT() asm volatile("cp.async.commit_group;" ::: "memory")
#define CP_WAIT0()  asm volatile("cp.async.wait_group 0;" ::: "memory")
#define CP_WAIT1()  asm volatile("cp.async.wait_group 1;" ::: "memory")

#define LDSM4(r0, r1, r2, r3, a) \
    asm volatile("ldmatrix.sync.aligned.m8n8.x4.shared.b16 {%0,%1,%2,%3}, [%4];" \
        : "=r"(r0), "=r"(r1), "=r"(r2), "=r"(r3) : "r"(a))

#define MMA_FP16(d, a, b) \
    asm volatile("mma.sync.aligned.m16n8k16.row.col.f32.f16.f16.f32 " \
        "{%0,%1,%2,%3}, {%4,%5,%6,%7}, {%8,%9}, {%0,%1,%2,%3};" \
        : "+f"((d)[0]), "+f"((d)[1]), "+f"((d)[2]), "+f"((d)[3]) \
        : "r"((a)[0]), "r"((a)[1]), "r"((a)[2]), "r"((a)[3]), \
          "r"((b)[0]), "r"((b)[1]))

// ======================= fused prep kernel =======================
__global__ void k_prep(const float* __restrict__ x, const float* __restrict__ Wq,
                       const float* __restrict__ Wk, const float* __restrict__ Wv,
                       __half* __restrict__ xhf, __half* __restrict__ xlf,
                       __half* __restrict__ xTf,
                       __half* __restrict__ wqktf, __half* __restrict__ wvtf)
{
    int b = blockIdx.x;
    const int tid = threadIdx.x;
    if (b < 1024) {
        int i0 = b * 2048 + tid;
#pragma unroll
        for (int q = 0; q < 8; ++q) {
            int i = i0 + q * 256;
            float v = x[i];
            __half h = __float2half_rn(v);
            __half l = __float2half_rn(v - __half2float(h));
            xhf[i] = h; xlf[i] = l;
        }
        return;
    }
    b -= 1024;
    const float* in; int R, C, bx, by;
    __half* oh;
    if (b < 256)      { in = Wq; oh = wqktf; R = 256;  C = 1024; bx = b & 31; by = b >> 5; }
    else if (b < 512) { b -= 256; in = Wk; oh = wqktf + (size_t)HD * DIM;
                        R = 256; C = 1024; bx = b & 31; by = b >> 5; }
    else if (b < 768) { b -= 512; in = Wv; oh = wvtf; R = 1024; C = 256; bx = b & 7; by = b >> 3; }
    else {
        b -= 768;
        int z = b >> 9, t = b & 511;
        in = x + (size_t)z * SEQ * DIM;
        oh = xTf + (size_t)z * DIM * SEQ;
        R = 2048; C = 256; bx = t & 7; by = t >> 3;
    }

    __shared__ float tbuf[32][33];
    const int tx = tid & 31, ty = tid >> 5;
    const int c0 = bx * 32, r0 = by * 32;
#pragma unroll
    for (int i = 0; i < 4; ++i)
        tbuf[ty + i * 8][tx] = in[(size_t)(r0 + ty + i * 8) * C + c0 + tx];
    __syncthreads();
#pragma unroll
    for (int i = 0; i < 4; ++i) {
        float v = tbuf[tx][ty + i * 8];
        oh[(size_t)(c0 + ty + i * 8) * R + r0 + tx] = __float2half_rn(v);
    }
}

// ======================= warp-MMA GEMM, cp.async pipeline, Kc=64 ====================
// MODE 4: proj Q+K (fp16 A-split 2-product, 2-stage, BN=128, 2 CTA/SM)
// MODE 1: scores (fp16 1-product, 3-stage, BN=128) -> fp16 exp(s/16) + row partials
// MODE 2: pv     (fp16 1-product, 3-stage, BN=128) -> fp16 att scaled by inv;
//                x=0 blocks also emit fp32 probs = Ef * inv from staged smem
// MODE 3: wv     (fp16 1-product, 2-stage, BN=256) -> residual + fused LayerNorm
template<int MODE, int BN>
__global__ void __launch_bounds__(256, (BN == 256) ? 1 : 2)
k_mma(const uint8_t* __restrict__ Ah, const uint8_t* __restrict__ Al,
      const uint8_t* __restrict__ Bh,
      int lda, int ldb, int K,
      size_t strideAz, size_t strideBz, int bShift,
      float* __restrict__ ep_f, void* __restrict__ ep_a,
      const float* __restrict__ resid,
      const float* __restrict__ gamma, const float* __restrict__ beta,
      size_t strideEz)
{
    constexpr bool PROJ   = (MODE == 4);
    constexpr int  WNT    = BN / 4;
    constexpr int  NBN    = BN / 32;
    constexpr int  NBL    = BN / 64;
    constexpr int  STAGE  = PROJ ? 49152 : (16384 + BN * 128);
    constexpr int  NSTAGE = (!PROJ && BN == 128) ? 3 : 2;
    extern __shared__ __align__(1024) char smem[];
    const uint32_t sb = smem_u32(smem);
    const int tid = threadIdx.x;
    const int wid = tid >> 5, lane = tid & 31;
    const int wm = wid >> 2, wn = wid & 3;
    const int mBase = blockIdx.y * 128, nBase = blockIdx.x * BN;
    const int z = blockIdx.z;

    const uint8_t* A0 = Ah + (size_t)z * strideAz * 2;
    const uint8_t* A1 = PROJ ? Al + (size_t)z * strideAz * 2 : nullptr;
    const uint8_t* B0 = Bh + (size_t)(z >> bShift) * strideBz * 2;

    const int nch = K >> 6;

    // MODE 2: per-row inverse sums (deterministic fixed-order, same as old k_rowinv)
    float* sinv = reinterpret_cast<float*>(smem + NSTAGE * STAGE);
    if (MODE == 2 && tid < 128) {
        const float* pp = resid + (size_t)z * 16 * SEQ + (mBase + tid);
        float s = 0.f;
#pragma unroll
        for (int jt = 0; jt < 16; ++jt) s += pp[(size_t)jt * SEQ];
        sinv[tid] = 1.0f / s;
    }

#define LOAD_TILE(srcB, ldE, rowB, k0, dstOff, ROWS)                                  \
    { _Pragma("unroll") for (int p_ = 0; p_ < (ROWS) / 32; ++p_) {                    \
        int idx_ = tid + 256 * p_;                                                    \
        int row_ = idx_ >> 3, c16_ = idx_ & 7;                                        \
        const uint8_t* g_ = (srcB) +                                                  \
            ((size_t)((rowB) + row_) * (ldE) + (k0) + c16_ * 8) * 2;                  \
        uint32_t d_ = sb + (dstOff) + row_ * 128 +                                    \
                      ((c16_ * 16) ^ ((row_ & 7) << 4));                              \
        CP16(d_, g_); } }

#define LOAD_CHUNK(i_, s_)                                                            \
    {                                                                                 \
        const int k0_ = (i_) * 64;                                                    \
        const int so_ = (s_) * STAGE;                                                 \
        if (PROJ) {                                                                   \
            LOAD_TILE(A0, lda, mBase, k0_, so_, 128);                                 \
            LOAD_TILE(A1, lda, mBase, k0_, so_ + 16384, 128);                         \
            LOAD_TILE(B0, ldb, nBase, k0_, so_ + 32768, 128);                         \
        } else {                                                                      \
            LOAD_TILE(A0, lda, mBase, k0_, so_, 128);                                 \
            LOAD_TILE(B0, ldb, nBase, k0_, so_ + 16384, BN);                          \
        }                                                                             \
        CP_COMMIT();                                                                  \
    }

    const int lrow = (lane & 7) + ((lane >> 3) & 1) * 8;
    const int kh16 = ((lane >> 4) & 1) * 16;
    const int swz  = (lane & 7) << 4;
    int rA[4], rB[NBL];
#pragma unroll
    for (int bm = 0; bm < 4; ++bm) rA[bm] = (wm * 64 + bm * 16 + lrow) * 128;
#pragma unroll
    for (int nb = 0; nb < NBL; ++nb) rB[nb] = (wn * WNT + nb * 16 + lrow) * 128;

    float acc[4][NBN][4];
#pragma unroll
    for (int a = 0; a < 4; ++a)
#pragma unroll
        for (int b = 0; b < NBN; ++b)
#pragma unroll
            for (int c = 0; c < 4; ++c) acc[a][b][c] = 0.f;

#pragma unroll
    for (int p = 0; p < NSTAGE - 1; ++p)
        if (p < nch) LOAD_CHUNK(p, p);

    int st = 0;
    for (int i = 0; i < nch; ++i) {
        const int rem = nch - 1 - i;
        if (NSTAGE == 3) {
            if (rem >= 1) { CP_WAIT1(); } else { CP_WAIT0(); }
        } else {
            CP_WAIT0();
        }
        __syncthreads();
        if (i + NSTAGE - 1 < nch) {
            int s2 = st + NSTAGE - 1; if (s2 >= NSTAGE) s2 -= NSTAGE;
            LOAD_CHUNK(i + NSTAGE - 1, s2);
        }

        // MODE 2, x=0 blocks: emit fp32 probs for this staged Ef chunk
        if (MODE == 2 && blockIdx.x == 0) {
            const int k0 = i * 64;
#pragma unroll
            for (int p = 0; p < 4; ++p) {
                int idx = tid + 256 * p;
                int row = idx >> 3, c16 = idx & 7;
                const uint4 u = *reinterpret_cast<const uint4*>(
                    smem + st * STAGE + row * 128 + ((c16 * 16) ^ ((row & 7) << 4)));
                const float iv = sinv[row];
                float2 f0 = __half22float2(*reinterpret_cast<const __half2*>(&u.x));
                float2 f1 = __half22float2(*reinterpret_cast<const __half2*>(&u.y));
                float2 f2 = __half22float2(*reinterpret_cast<const __half2*>(&u.z));
                float2 f3 = __half22float2(*reinterpret_cast<const __half2*>(&u.w));
                float4 o0, o1;
                o0.x = f0.x * iv; o0.y = f0.y * iv; o0.z = f1.x * iv; o0.w = f1.y * iv;
                o1.x = f2.x * iv; o1.y = f2.y * iv; o1.z = f3.x * iv; o1.w = f3.y * iv;
                float* dst = ep_f + (size_t)z * strideEz +
                             (size_t)(mBase + row) * SEQ + k0 + c16 * 8;
                *reinterpret_cast<float4*>(dst)     = o0;
                *reinterpret_cast<float4*>(dst + 4) = o1;
            }
        }

        const uint32_t so = sb + st * STAGE;
        const uint32_t sA  = so;
        const uint32_t sAl = so + 16384;
        const uint32_t sB  = so + (PROJ ? 32768 : 16384);

#pragma unroll
        for (int ks = 0; ks < 4; ++ks) {
            const int cz = ((ks * 32) + kh16) ^ swz;
            uint32_t ah[4][4];
#pragma unroll
            for (int bm = 0; bm < 4; ++bm)
                LDSM4(ah[bm][0], ah[bm][1], ah[bm][2], ah[bm][3], sA + rA[bm] + cz);
            uint32_t bh[NBN][2];
#pragma unroll
            for (int nb = 0; nb < NBL; ++nb) {
                uint32_t t0, t1, t2, t3;
                LDSM4(t0, t1, t2, t3, sB + rB[nb] + cz);
                bh[nb * 2][0] = t0; bh[nb * 2][1] = t2;
                bh[nb * 2 + 1][0] = t1; bh[nb * 2 + 1][1] = t3;
            }
#pragma unroll
            for (int bm = 0; bm < 4; ++bm)
#pragma unroll
                for (int bn = 0; bn < NBN; ++bn) MMA_FP16(acc[bm][bn], ah[bm], bh[bn]);
            if (PROJ) {
                uint32_t al[4][4];
#pragma unroll
                for (int bm = 0; bm < 4; ++bm)
                    LDSM4(al[bm][0], al[bm][1], al[bm][2], al[bm][3], sAl + rA[bm] + cz);
#pragma unroll
                for (int bm = 0; bm < 4; ++bm)
#pragma unroll
                    for (int bn = 0; bn < NBN; ++bn) MMA_FP16(acc[bm][bn], al[bm], bh[bn]);
            }
        }
        if (++st == NSTAGE) st = 0;
        if (i + 1 < nch) __syncthreads();
    }
#undef LOAD_CHUNK
#undef LOAD_TILE

    // ======================= epilogue =======================
    const int g4 = lane >> 2, t4 = lane & 3;

    if (MODE == 1) {
        // exp(s/16) -> fp16 Ef + deterministic per-CTA row partial sums
        __syncthreads();
        float* rowp = reinterpret_cast<float*>(smem);   // [128][4]
        float rp[8];
#pragma unroll
        for (int r8 = 0; r8 < 8; ++r8) rp[r8] = 0.f;
#pragma unroll
        for (int bm = 0; bm < 4; ++bm)
#pragma unroll
            for (int half = 0; half < 2; ++half) {
                const int gr = mBase + wm * 64 + bm * 16 + g4 + half * 8;
                const int r8 = bm * 2 + half;
#pragma unroll
                for (int bn = 0; bn < NBN; ++bn) {
                    const int c0 = nBase + wn * WNT + bn * 8 + t4 * 2;
                    float e0 = __expf(acc[bm][bn][half * 2 + 0] * 0.0625f);
                    float e1 = __expf(acc[bm][bn][half * 2 + 1] * 0.0625f);
                    *reinterpret_cast<__half2*>((__half*)ep_a +
                        (size_t)z * strideEz + (size_t)gr * SEQ + c0) =
                        __floats2half2_rn(e0, e1);
                    rp[r8] += e0 + e1;
                }
            }
#pragma unroll
        for (int r8 = 0; r8 < 8; ++r8) {
            rp[r8] += __shfl_xor_sync(~0u, rp[r8], 1);
            rp[r8] += __shfl_xor_sync(~0u, rp[r8], 2);
        }
        if (t4 == 0) {
#pragma unroll
            for (int bm = 0; bm < 4; ++bm)
#pragma unroll
                for (int half = 0; half < 2; ++half) {
                    const int lr = wm * 64 + bm * 16 + g4 + half * 8;
                    rowp[lr * 4 + wn] = rp[bm * 2 + half];
                }
        }
        __syncthreads();
        if (tid < 128) {
            float s = rowp[tid * 4] + rowp[tid * 4 + 1]
                    + rowp[tid * 4 + 2] + rowp[tid * 4 + 3];
            ep_f[((size_t)z * 16 + blockIdx.x) * SEQ + mBase + tid] = s;
        }
        return;
    }

    if (MODE == 3) {
        // ---- fused residual + LayerNorm (BN == 256 covers the full row) ----
        __syncthreads();
        float2* part = reinterpret_cast<float2*>(smem);          // [128][16]
        float*  musg = reinterpret_cast<float*>(smem + 16384);   // [128][2]
        const int slice = wn * 4 + t4;

        float psum[8], psq[8];
#pragma unroll
        for (int r8 = 0; r8 < 8; ++r8) { psum[r8] = 0.f; psq[r8] = 0.f; }
#pragma unroll
        for (int bm = 0; bm < 4; ++bm)
#pragma unroll
            for (int half = 0; half < 2; ++half) {
                const int gr = mBase + wm * 64 + bm * 16 + g4 + half * 8;
                const int r8 = bm * 2 + half;
#pragma unroll
                for (int bn = 0; bn < NBN; ++bn) {
                    const int c0 = wn * WNT + bn * 8 + t4 * 2;
                    float2 rx = *reinterpret_cast<const float2*>(
                        resid + (size_t)gr * DIM + c0);
                    float v0 = acc[bm][bn][half * 2 + 0] + rx.x;
                    float v1 = acc[bm][bn][half * 2 + 1] + rx.y;
                    psum[r8] += v0 + v1;
                    psq[r8]  += v0 * v0 + v1 * v1;
                }
            }
#pragma unroll
        for (int bm = 0; bm < 4; ++bm)
#pragma unroll
            for (int half = 0; half < 2; ++half) {
                const int lr = wm * 64 + bm * 16 + g4 + half * 8;
                const int r8 = bm * 2 + half;
                float2 p; p.x = psum[r8]; p.y = psq[r8];
                part[lr * 16 + slice] = p;
            }
        __syncthreads();
        if (tid < 128) {
            float s = 0.f, q = 0.f;
#pragma unroll
            for (int k = 0; k < 16; ++k) {
                float2 p = part[tid * 16 + k];
                s += p.x; q += p.y;
            }
            float mu  = s * (1.0f / 256.0f);
            float var = q * (1.0f / 256.0f) - mu * mu;
            musg[tid * 2]     = mu;
            musg[tid * 2 + 1] = rsqrtf(var + 1e-5f);
        }
        __syncthreads();
#pragma unroll
        for (int bm = 0; bm < 4; ++bm)
#pragma unroll
            for (int half = 0; half < 2; ++half) {
                const int lr = wm * 64 + bm * 16 + g4 + half * 8;
                const int gr = mBase + lr;
                const float mu  = musg[lr * 2];
                const float inv = musg[lr * 2 + 1];
#pragma unroll
                for (int bn = 0; bn < NBN; ++bn) {
                    const int c0 = wn * WNT + bn * 8 + t4 * 2;
                    size_t off = (size_t)gr * DIM + c0;
                    float2 rx = *reinterpret_cast<const float2*>(resid + off);
                    float v0 = acc[bm][bn][half * 2 + 0] + rx.x;
                    float v1 = acc[bm][bn][half * 2 + 1] + rx.y;
                    float2 gb0 = *reinterpret_cast<const float2*>(gamma + c0);
                    float2 bb0 = *reinterpret_cast<const float2*>(beta + c0);
                    float2 o;
                    o.x = (v0 - mu) * inv * gb0.x + bb0.x;
                    o.y = (v1 - mu) * inv * gb0.y + bb0.y;
                    *reinterpret_cast<float2*>(ep_f + off) = o;
                }
            }
        return;
    }

#pragma unroll
    for (int bm = 0; bm < 4; ++bm) {
#pragma unroll
        for (int bn = 0; bn < NBN; ++bn) {
            const int r0 = mBase + wm * 64 + bm * 16 + g4;
            const int c0 = nBase + wn * WNT + bn * 8 + t4 * 2;
            const float* a4 = acc[bm][bn];
#pragma unroll
            for (int half = 0; half < 2; ++half) {
                const int gr = r0 + half * 8;
                const float v0 = a4[half * 2 + 0];
                const float v1 = a4[half * 2 + 1];
                if (MODE == 4) {
                    const int bb = gr >> 11, rr = gr & 2047;
                    const int hh = rr >> 9, ib = (rr & 511) << 2;
                    const int ii = ib | (c0 >> 8), dd = c0 & 255;
                    size_t base = (size_t)z * strideEz +
                                  ((size_t)(bb * 4 + hh) * SEQ + ii) * DIM + dd;
                    *reinterpret_cast<__half2*>((__half*)ep_a + base) =
                        __floats2half2_rn(v0, v1);
                } else {  // MODE 2: att scaled by row inv (from smem)
                    const float sc = sinv[gr - mBase];
                    const int bb = z >> 2, h = z & 3;
                    size_t base = ((size_t)(bb * SEQ + gr)) * HD + h * DIM + c0;
                    *reinterpret_cast<__half2*>((__half*)ep_a + base) =
                        __floats2half2_rn(v0 * sc, v1 * sc);
                }
            }
        }
    }
}

// ======================= launch =======================
extern "C" void kernel_launch(void* const* d_in, const int* in_sizes, int n_in,
                              void* d_out, int out_size)
{
    const float* x     = (const float*)d_in[0];
    const float* Wq    = (const float*)d_in[1];
    const float* Wk    = (const float*)d_in[2];
    const float* Wv    = (const float*)d_in[3];
    const float* gamma = (const float*)d_in[4];
    const float* beta  = (const float*)d_in[5];

    __half *xhf, *xlf, *xTf, *wqktf, *wvtf, *QKf, *Ef, *attf;
    float *part, *outFb, *probsFb;
    cudaGetSymbolAddress((void**)&xhf, g_xhf);     cudaGetSymbolAddress((void**)&xlf, g_xlf);
    cudaGetSymbolAddress((void**)&xTf, g_xTf);
    cudaGetSymbolAddress((void**)&wqktf, g_wqktf); cudaGetSymbolAddress((void**)&wvtf, g_wvtf);
    cudaGetSymbolAddress((void**)&QKf, g_QKf);
    cudaGetSymbolAddress((void**)&Ef, g_Ef);
    cudaGetSymbolAddress((void**)&part, g_part);
    cudaGetSymbolAddress((void**)&attf, g_attf);
    cudaGetSymbolAddress((void**)&outFb, g_out_fb);
    cudaGetSymbolAddress((void**)&probsFb, g_probs_fb);

    const long long OUT_E = (long long)BS * SEQ * DIM;
    const long long PR_E  = (long long)BHN * SEQ * SEQ;
    long long osz = out_size;
    float *outp, *probs;
    if (osz >= OUT_E + PR_E) { outp = (float*)d_out; probs = (float*)d_out + OUT_E; }
    else if (osz >= PR_E)    { probs = (float*)d_out; outp = outFb; }
    else                     { outp = (float*)d_out; probs = probsFb; }

    cudaFuncSetAttribute((const void*)k_mma<4, 128>, cudaFuncAttributeMaxDynamicSharedMemorySize, 98304);
    cudaFuncSetAttribute((const void*)k_mma<1, 128>, cudaFuncAttributeMaxDynamicSharedMemorySize, 98304);
    cudaFuncSetAttribute((const void*)k_mma<2, 128>, cudaFuncAttributeMaxDynamicSharedMemorySize, 99328);
    cudaFuncSetAttribute((const void*)k_mma<3, 256>, cudaFuncAttributeMaxDynamicSharedMemorySize, 98304);

    dim3 T(256);
    const size_t QK_Z = (size_t)BHN * SEQ * DIM;

    // 1: fused prep
    k_prep<<<3840, T>>>(x, Wq, Wk, Wv, xhf, xlf, xTf, wqktf, wvtf);

    // 2: Q+K projections merged (z=0 -> Qf, z=1 -> Kf), fp16 2-product
    k_mma<4, 128><<<dim3(8, 64, 2), T, 98304>>>((const uint8_t*)xhf, (const uint8_t*)xlf,
        (const uint8_t*)wqktf, 256, 256, 256,
        0, (size_t)HD * DIM, 0, nullptr, QKf, nullptr, nullptr, nullptr, QK_Z);

    // 3: scores -> exp fp16 (Ef) + row partial sums
    k_mma<1, 128><<<dim3(16, 16, BHN), T, 98304>>>((const uint8_t*)QKf, nullptr,
        (const uint8_t*)(QKf + QK_Z), 256, 256, 256,
        (size_t)SEQ * DIM, (size_t)SEQ * DIM, 0,
        part, Ef, nullptr, nullptr, nullptr, (size_t)SEQ * SEQ);

    // 4: PV (reads Ef; computes inv in-kernel; x=0 blocks emit fp32 probs;
    //        att rows scaled by inv)
    k_mma<2, 128><<<dim3(2, 16, BHN), T, 99328>>>((const uint8_t*)Ef, nullptr,
        (const uint8_t*)xTf, 2048, 2048, 2048,
        (size_t)SEQ * SEQ, (size_t)DIM * SEQ, 2,
        probs, attf, part, nullptr, nullptr, (size_t)SEQ * SEQ);

    // 5: att @ Wv + x -> LayerNorm -> out, fused epilogue
    k_mma<3, 256><<<dim3(1, 64, 1), T, 98304>>>((const uint8_t*)attf, nullptr,
        (const uint8_t*)wvtf, 1024, 1024, 1024,
        0, 0, 0, outp, nullptr, x, gamma, beta, 0);
}

// round 16
// speedup vs baseline: 1.1146x; 1.0177x over previous
#include <cuda_runtime.h>
#include <cuda_bf16.h>
#include <cuda_fp16.h>
#include <cstdint>
#include <cstddef>

#define BS   4
#define SEQ  2048
#define DIM  256
#define HH   4
#define HD   1024
#define BHN  16

// ======================= device scratch =======================
__device__ __align__(256) __half g_xhf [(size_t)BS*SEQ*DIM];
__device__ __align__(256) __half g_xlf [(size_t)BS*SEQ*DIM];
__device__ __align__(256) __half g_xTf [(size_t)BS*DIM*SEQ];
__device__ __align__(256) __half g_wqktf[(size_t)2*HD*DIM];
__device__ __align__(256) __half g_wvtf[(size_t)DIM*HD];
__device__ __align__(256) __half g_QKf [(size_t)2*BHN*SEQ*DIM];
__device__ __align__(256) __half g_Ef  [(size_t)BHN*SEQ*SEQ];     // fp16 exp(scores)
__device__ __align__(256) float  g_part[(size_t)BHN*16*SEQ];      // per-jtile row partials
__device__ __align__(256) __half g_attf[(size_t)BS*SEQ*HD];
__device__ __align__(256) float  g_out_fb [(size_t)BS*SEQ*DIM];
__device__ __align__(256) float  g_probs_fb[(size_t)BHN*SEQ*SEQ];

// ======================= helpers =======================
__device__ __forceinline__ uint32_t smem_u32(const void* p) {
    uint32_t a;
    asm("{ .reg .u64 t; cvta.to.shared.u64 t, %1; cvt.u32.u64 %0, t; }" : "=r"(a) : "l"(p));
    return a;
}
#define CP16(dst, src) \
    asm volatile("cp.async.cg.shared.global [%0], [%1], 16;" :: "r"(dst), "l"(src))
#define CP_COMMIT() asm volatile("cp.async.commit_group;" ::: "memory")
#define CP_WAIT0()  asm volatile("cp.async.wait_group 0;" ::: "memory")
#define CP_WAIT1()  asm volatile("cp.async.wait_group 1;" ::: "memory")

#define LDSM4(r0, r1, r2, r3, a) \
    asm volatile("ldmatrix.sync.aligned.m8n8.x4.shared.b16 {%0,%1,%2,%3}, [%4];" \
        : "=r"(r0), "=r"(r1), "=r"(r2), "=r"(r3) : "r"(a))

#define MMA_FP16(d, a, b) \
    asm volatile("mma.sync.aligned.m16n8k16.row.col.f32.f16.f16.f32 " \
        "{%0,%1,%2,%3}, {%4,%5,%6,%7}, {%8,%9}, {%0,%1,%2,%3};" \
        : "+f"((d)[0]), "+f"((d)[1]), "+f"((d)[2]), "+f"((d)[3]) \
        : "r"((a)[0]), "r"((a)[1]), "r"((a)[2]), "r"((a)[3]), \
          "r"((b)[0]), "r"((b)[1]))

// ======================= fused prep kernel =======================
__global__ void k_prep(const float* __restrict__ x, const float* __restrict__ Wq,
                       const float* __restrict__ Wk, const float* __restrict__ Wv,
                       __half* __restrict__ xhf, __half* __restrict__ xlf,
                       __half* __restrict__ xTf,
                       __half* __restrict__ wqktf, __half* __restrict__ wvtf)
{
    int b = blockIdx.x;
    const int tid = threadIdx.x;
    if (b < 1024) {
        int i0 = b * 2048 + tid;
#pragma unroll
        for (int q = 0; q < 8; ++q) {
            int i = i0 + q * 256;
            float v = x[i];
            __half h = __float2half_rn(v);
            __half l = __float2half_rn(v - __half2float(h));
            xhf[i] = h; xlf[i] = l;
        }
        return;
    }
    b -= 1024;
    const float* in; int R, C, bx, by;
    __half* oh;
    if (b < 256)      { in = Wq; oh = wqktf; R = 256;  C = 1024; bx = b & 31; by = b >> 5; }
    else if (b < 512) { b -= 256; in = Wk; oh = wqktf + (size_t)HD * DIM;
                        R = 256; C = 1024; bx = b & 31; by = b >> 5; }
    else if (b < 768) { b -= 512; in = Wv; oh = wvtf; R = 1024; C = 256; bx = b & 7; by = b >> 3; }
    else {
        b -= 768;
        int z = b >> 9, t = b & 511;
        in = x + (size_t)z * SEQ * DIM;
        oh = xTf + (size_t)z * DIM * SEQ;
        R = 2048; C = 256; bx = t & 7; by = t >> 3;
    }

    __shared__ float tbuf[32][33];
    const int tx = tid & 31, ty = tid >> 5;
    const int c0 = bx * 32, r0 = by * 32;
#pragma unroll
    for (int i = 0; i < 4; ++i)
        tbuf[ty + i * 8][tx] = in[(size_t)(r0 + ty + i * 8) * C + c0 + tx];
    __syncthreads();
#pragma unroll
    for (int i = 0; i < 4; ++i) {
        float v = tbuf[tx][ty + i * 8];
        oh[(size_t)(c0 + ty + i * 8) * R + r0 + tx] = __float2half_rn(v);
    }
}

// ======================= warp-MMA GEMM, cp.async pipeline, Kc=64 ====================
// MODE 4: proj Q+K (fp16 A-split 2-product, 2-stage, BN=128, 2 CTA/SM)
// MODE 1: scores (fp16 1-product, 3-stage, BN=128) -> fp16 exp(s/16) + row partials
// MODE 2: pv     (fp16 1-product, 3-stage, BN=128) -> fp16 att scaled by inv;
//                probs emission split by chunk parity across the two x-blocks
// MODE 3: wv     (fp16 1-product, 2-stage, BN=256) -> residual + fused LayerNorm
template<int MODE, int BN>
__global__ void __launch_bounds__(256, (BN == 256) ? 1 : 2)
k_mma(const uint8_t* __restrict__ Ah, const uint8_t* __restrict__ Al,
      const uint8_t* __restrict__ Bh,
      int lda, int ldb, int K,
      size_t strideAz, size_t strideBz, int bShift,
      float* __restrict__ ep_f, void* __restrict__ ep_a,
      const float* __restrict__ resid,
      const float* __restrict__ gamma, const float* __restrict__ beta,
      size_t strideEz)
{
    constexpr bool PROJ   = (MODE == 4);
    constexpr int  WNT    = BN / 4;
    constexpr int  NBN    = BN / 32;
    constexpr int  NBL    = BN / 64;
    constexpr int  STAGE  = PROJ ? 49152 : (16384 + BN * 128);
    constexpr int  NSTAGE = (!PROJ && BN == 128) ? 3 : 2;
    extern __shared__ __align__(1024) char smem[];
    const uint32_t sb = smem_u32(smem);
    const int tid = threadIdx.x;
    const int wid = tid >> 5, lane = tid & 31;
    const int wm = wid >> 2, wn = wid & 3;
    const int mBase = blockIdx.y * 128, nBase = blockIdx.x * BN;
    const int z = blockIdx.z;

    const uint8_t* A0 = Ah + (size_t)z * strideAz * 2;
    const uint8_t* A1 = PROJ ? Al + (size_t)z * strideAz * 2 : nullptr;
    const uint8_t* B0 = Bh + (size_t)(z >> bShift) * strideBz * 2;

    const int nch = K >> 6;

    // MODE 2: per-row inverse sums (deterministic fixed-order)
    float* sinv = reinterpret_cast<float*>(smem + NSTAGE * STAGE);
    if (MODE == 2 && tid < 128) {
        const float* pp = resid + (size_t)z * 16 * SEQ + (mBase + tid);
        float s = 0.f;
#pragma unroll
        for (int jt = 0; jt < 16; ++jt) s += pp[(size_t)jt * SEQ];
        sinv[tid] = 1.0f / s;
    }

#define LOAD_TILE(srcB, ldE, rowB, k0, dstOff, ROWS)                                  \
    { _Pragma("unroll") for (int p_ = 0; p_ < (ROWS) / 32; ++p_) {                    \
        int idx_ = tid + 256 * p_;                                                    \
        int row_ = idx_ >> 3, c16_ = idx_ & 7;                                        \
        const uint8_t* g_ = (srcB) +                                                  \
            ((size_t)((rowB) + row_) * (ldE) + (k0) + c16_ * 8) * 2;                  \
        uint32_t d_ = sb + (dstOff) + row_ * 128 +                                    \
                      ((c16_ * 16) ^ ((row_ & 7) << 4));                              \
        CP16(d_, g_); } }

#define LOAD_CHUNK(i_, s_)                                                            \
    {                                                                                 \
        const int k0_ = (i_) * 64;                                                    \
        const int so_ = (s_) * STAGE;                                                 \
        if (PROJ) {                                                                   \
            LOAD_TILE(A0, lda, mBase, k0_, so_, 128);                                 \
            LOAD_TILE(A1, lda, mBase, k0_, so_ + 16384, 128);                         \
            LOAD_TILE(B0, ldb, nBase, k0_, so_ + 32768, 128);                         \
        } else {                                                                      \
            LOAD_TILE(A0, lda, mBase, k0_, so_, 128);                                 \
            LOAD_TILE(B0, ldb, nBase, k0_, so_ + 16384, BN);                          \
        }                                                                             \
        CP_COMMIT();                                                                  \
    }

    const int lrow = (lane & 7) + ((lane >> 3) & 1) * 8;
    const int kh16 = ((lane >> 4) & 1) * 16;
    const int swz  = (lane & 7) << 4;
    int rA[4], rB[NBL];
#pragma unroll
    for (int bm = 0; bm < 4; ++bm) rA[bm] = (wm * 64 + bm * 16 + lrow) * 128;
#pragma unroll
    for (int nb = 0; nb < NBL; ++nb) rB[nb] = (wn * WNT + nb * 16 + lrow) * 128;

    float acc[4][NBN][4];
#pragma unroll
    for (int a = 0; a < 4; ++a)
#pragma unroll
        for (int b = 0; b < NBN; ++b)
#pragma unroll
            for (int c = 0; c < 4; ++c) acc[a][b][c] = 0.f;

#pragma unroll
    for (int p = 0; p < NSTAGE - 1; ++p)
        if (p < nch) LOAD_CHUNK(p, p);

    int st = 0;
    for (int i = 0; i < nch; ++i) {
        const int rem = nch - 1 - i;
        if (NSTAGE == 3) {
            if (rem >= 1) { CP_WAIT1(); } else { CP_WAIT0(); }
        } else {
            CP_WAIT0();
        }
        __syncthreads();
        if (i + NSTAGE - 1 < nch) {
            int s2 = st + NSTAGE - 1; if (s2 >= NSTAGE) s2 -= NSTAGE;
            LOAD_CHUNK(i + NSTAGE - 1, s2);
        }

        // MODE 2: emit fp32 probs for this staged Ef chunk, split by chunk parity
        if (MODE == 2 && (int)blockIdx.x == (i & 1)) {
            const int k0 = i * 64;
#pragma unroll
            for (int p = 0; p < 4; ++p) {
                int idx = tid + 256 * p;
                int row = idx >> 3, c16 = idx & 7;
                const uint4 u = *reinterpret_cast<const uint4*>(
                    smem + st * STAGE + row * 128 + ((c16 * 16) ^ ((row & 7) << 4)));
                const float iv = sinv[row];
                float2 f0 = __half22float2(*reinterpret_cast<const __half2*>(&u.x));
                float2 f1 = __half22float2(*reinterpret_cast<const __half2*>(&u.y));
                float2 f2 = __half22float2(*reinterpret_cast<const __half2*>(&u.z));
                float2 f3 = __half22float2(*reinterpret_cast<const __half2*>(&u.w));
                float4 o0, o1;
                o0.x = f0.x * iv; o0.y = f0.y * iv; o0.z = f1.x * iv; o0.w = f1.y * iv;
                o1.x = f2.x * iv; o1.y = f2.y * iv; o1.z = f3.x * iv; o1.w = f3.y * iv;
                float* dst = ep_f + (size_t)z * strideEz +
                             (size_t)(mBase + row) * SEQ + k0 + c16 * 8;
                *reinterpret_cast<float4*>(dst)     = o0;
                *reinterpret_cast<float4*>(dst + 4) = o1;
            }
        }

        const uint32_t so = sb + st * STAGE;
        const uint32_t sA  = so;
        const uint32_t sAl = so + 16384;
        const uint32_t sB  = so + (PROJ ? 32768 : 16384);

#pragma unroll
        for (int ks = 0; ks < 4; ++ks) {
            const int cz = ((ks * 32) + kh16) ^ swz;
            uint32_t ah[4][4];
#pragma unroll
            for (int bm = 0; bm < 4; ++bm)
                LDSM4(ah[bm][0], ah[bm][1], ah[bm][2], ah[bm][3], sA + rA[bm] + cz);
            uint32_t bh[NBN][2];
#pragma unroll
            for (int nb = 0; nb < NBL; ++nb) {
                uint32_t t0, t1, t2, t3;
                LDSM4(t0, t1, t2, t3, sB + rB[nb] + cz);
                bh[nb * 2][0] = t0; bh[nb * 2][1] = t2;
                bh[nb * 2 + 1][0] = t1; bh[nb * 2 + 1][1] = t3;
            }
#pragma unroll
            for (int bm = 0; bm < 4; ++bm)
#pragma unroll
                for (int bn = 0; bn < NBN; ++bn) MMA_FP16(acc[bm][bn], ah[bm], bh[bn]);
            if (PROJ) {
                uint32_t al[4][4];
#pragma unroll
                for (int bm = 0; bm < 4; ++bm)
                    LDSM4(al[bm][0], al[bm][1], al[bm][2], al[bm][3], sAl + rA[bm] + cz);
#pragma unroll
                for (int bm = 0; bm < 4; ++bm)
#pragma unroll
                    for (int bn = 0; bn < NBN; ++bn) MMA_FP16(acc[bm][bn], al[bm], bh[bn]);
            }
        }
        if (++st == NSTAGE) st = 0;
        if (i + 1 < nch) __syncthreads();
    }
#undef LOAD_CHUNK
#undef LOAD_TILE

    // ======================= epilogue =======================
    const int g4 = lane >> 2, t4 = lane & 3;

    if (MODE == 1) {
        // exp(s/16) -> fp16 Ef + deterministic per-CTA row partial sums
        __syncthreads();
        float* rowp = reinterpret_cast<float*>(smem);   // [128][4]
        float rp[8];
#pragma unroll
        for (int r8 = 0; r8 < 8; ++r8) rp[r8] = 0.f;
#pragma unroll
        for (int bm = 0; bm < 4; ++bm)
#pragma unroll
            for (int half = 0; half < 2; ++half) {
                const int gr = mBase + wm * 64 + bm * 16 + g4 + half * 8;
                const int r8 = bm * 2 + half;
#pragma unroll
                for (int bn = 0; bn < NBN; ++bn) {
                    const int c0 = nBase + wn * WNT + bn * 8 + t4 * 2;
                    float e0 = __expf(acc[bm][bn][half * 2 + 0] * 0.0625f);
                    float e1 = __expf(acc[bm][bn][half * 2 + 1] * 0.0625f);
                    *reinterpret_cast<__half2*>((__half*)ep_a +
                        (size_t)z * strideEz + (size_t)gr * SEQ + c0) =
                        __floats2half2_rn(e0, e1);
                    rp[r8] += e0 + e1;
                }
            }
#pragma unroll
        for (int r8 = 0; r8 < 8; ++r8) {
            rp[r8] += __shfl_xor_sync(~0u, rp[r8], 1);
            rp[r8] += __shfl_xor_sync(~0u, rp[r8], 2);
        }
        if (t4 == 0) {
#pragma unroll
            for (int bm = 0; bm < 4; ++bm)
#pragma unroll
                for (int half = 0; half < 2; ++half) {
                    const int lr = wm * 64 + bm * 16 + g4 + half * 8;
                    rowp[lr * 4 + wn] = rp[bm * 2 + half];
                }
        }
        __syncthreads();
        if (tid < 128) {
            float s = rowp[tid * 4] + rowp[tid * 4 + 1]
                    + rowp[tid * 4 + 2] + rowp[tid * 4 + 3];
            ep_f[((size_t)z * 16 + blockIdx.x) * SEQ + mBase + tid] = s;
        }
        return;
    }

    if (MODE == 3) {
        // ---- fused residual + LayerNorm (BN == 256 covers the full row) ----
        __syncthreads();
        float2* part = reinterpret_cast<float2*>(smem);          // [128][16]
        float*  musg = reinterpret_cast<float*>(smem + 16384);   // [128][2]
        const int slice = wn * 4 + t4;

        float psum[8], psq[8];
#pragma unroll
        for (int r8 = 0; r8 < 8; ++r8) { psum[r8] = 0.f; psq[r8] = 0.f; }
#pragma unroll
        for (int bm = 0; bm < 4; ++bm)
#pragma unroll
            for (int half = 0; half < 2; ++half) {
                const int gr = mBase + wm * 64 + bm * 16 + g4 + half * 8;
                const int r8 = bm * 2 + half;
#pragma unroll
                for (int bn = 0; bn < NBN; ++bn) {
                    const int c0 = wn * WNT + bn * 8 + t4 * 2;
                    float2 rx = *reinterpret_cast<const float2*>(
                        resid + (size_t)gr * DIM + c0);
                    float v0 = acc[bm][bn][half * 2 + 0] + rx.x;
                    float v1 = acc[bm][bn][half * 2 + 1] + rx.y;
                    psum[r8] += v0 + v1;
                    psq[r8]  += v0 * v0 + v1 * v1;
                }
            }
#pragma unroll
        for (int bm = 0; bm < 4; ++bm)
#pragma unroll
            for (int half = 0; half < 2; ++half) {
                const int lr = wm * 64 + bm * 16 + g4 + half * 8;
                const int r8 = bm * 2 + half;
                float2 p; p.x = psum[r8]; p.y = psq[r8];
                part[lr * 16 + slice] = p;
            }
        __syncthreads();
        if (tid < 128) {
            float s = 0.f, q = 0.f;
#pragma unroll
            for (int k = 0; k < 16; ++k) {
                float2 p = part[tid * 16 + k];
                s += p.x; q += p.y;
            }
            float mu  = s * (1.0f / 256.0f);
            float var = q * (1.0f / 256.0f) - mu * mu;
            musg[tid * 2]     = mu;
            musg[tid * 2 + 1] = rsqrtf(var + 1e-5f);
        }
        __syncthreads();
#pragma unroll
        for (int bm = 0; bm < 4; ++bm)
#pragma unroll
            for (int half = 0; half < 2; ++half) {
                const int lr = wm * 64 + bm * 16 + g4 + half * 8;
                const int gr = mBase + lr;
                const float mu  = musg[lr * 2];
                const float inv = musg[lr * 2 + 1];
#pragma unroll
                for (int bn = 0; bn < NBN; ++bn) {
                    const int c0 = wn * WNT + bn * 8 + t4 * 2;
                    size_t off = (size_t)gr * DIM + c0;
                    float2 rx = *reinterpret_cast<const float2*>(resid + off);
                    float v0 = acc[bm][bn][half * 2 + 0] + rx.x;
                    float v1 = acc[bm][bn][half * 2 + 1] + rx.y;
                    float2 gb0 = *reinterpret_cast<const float2*>(gamma + c0);
                    float2 bb0 = *reinterpret_cast<const float2*>(beta + c0);
                    float2 o;
                    o.x = (v0 - mu) * inv * gb0.x + bb0.x;
                    o.y = (v1 - mu) * inv * gb0.y + bb0.y;
                    *reinterpret_cast<float2*>(ep_f + off) = o;
                }
            }
        return;
    }

#pragma unroll
    for (int bm = 0; bm < 4; ++bm) {
#pragma unroll
        for (int bn = 0; bn < NBN; ++bn) {
            const int r0 = mBase + wm * 64 + bm * 16 + g4;
            const int c0 = nBase + wn * WNT + bn * 8 + t4 * 2;
            const float* a4 = acc[bm][bn];
#pragma unroll
            for (int half = 0; half < 2; ++half) {
                const int gr = r0 + half * 8;
                const float v0 = a4[half * 2 + 0];
                const float v1 = a4[half * 2 + 1];
                if (MODE == 4) {
                    const int bb = gr >> 11, rr = gr & 2047;
                    const int hh = rr >> 9, ib = (rr & 511) << 2;
                    const int ii = ib | (c0 >> 8), dd = c0 & 255;
                    size_t base = (size_t)z * strideEz +
                                  ((size_t)(bb * 4 + hh) * SEQ + ii) * DIM + dd;
                    *reinterpret_cast<__half2*>((__half*)ep_a + base) =
                        __floats2half2_rn(v0, v1);
                } else {  // MODE 2: att scaled by row inv (from smem)
                    const float sc = sinv[gr - mBase];
                    const int bb = z >> 2, h = z & 3;
                    size_t base = ((size_t)(bb * SEQ + gr)) * HD + h * DIM + c0;
                    *reinterpret_cast<__half2*>((__half*)ep_a + base) =
                        __floats2half2_rn(v0 * sc, v1 * sc);
                }
            }
        }
    }
}

// ======================= launch =======================
extern "C" void kernel_launch(void* const* d_in, const int* in_sizes, int n_in,
                              void* d_out, int out_size)
{
    const float* x     = (const float*)d_in[0];
    const float* Wq    = (const float*)d_in[1];
    const float* Wk    = (const float*)d_in[2];
    const float* Wv    = (const float*)d_in[3];
    const float* gamma = (const float*)d_in[4];
    const float* beta  = (const float*)d_in[5];

    __half *xhf, *xlf, *xTf, *wqktf, *wvtf, *QKf, *Ef, *attf;
    float *part, *outFb, *probsFb;
    cudaGetSymbolAddress((void**)&xhf, g_xhf);     cudaGetSymbolAddress((void**)&xlf, g_xlf);
    cudaGetSymbolAddress((void**)&xTf, g_xTf);
    cudaGetSymbolAddress((void**)&wqktf, g_wqktf); cudaGetSymbolAddress((void**)&wvtf, g_wvtf);
    cudaGetSymbolAddress((void**)&QKf, g_QKf);
    cudaGetSymbolAddress((void**)&Ef, g_Ef);
    cudaGetSymbolAddress((void**)&part, g_part);
    cudaGetSymbolAddress((void**)&attf, g_attf);
    cudaGetSymbolAddress((void**)&outFb, g_out_fb);
    cudaGetSymbolAddress((void**)&probsFb, g_probs_fb);

    const long long OUT_E = (long long)BS * SEQ * DIM;
    const long long PR_E  = (long long)BHN * SEQ * SEQ;
    long long osz = out_size;
    float *outp, *probs;
    if (osz >= OUT_E + PR_E) { outp = (float*)d_out; probs = (float*)d_out + OUT_E; }
    else if (osz >= PR_E)    { probs = (float*)d_out; outp = outFb; }
    else                     { outp = (float*)d_out; probs = probsFb; }

    cudaFuncSetAttribute((const void*)k_mma<4, 128>, cudaFuncAttributeMaxDynamicSharedMemorySize, 98304);
    cudaFuncSetAttribute((const void*)k_mma<1, 128>, cudaFuncAttributeMaxDynamicSharedMemorySize, 98304);
    cudaFuncSetAttribute((const void*)k_mma<2, 128>, cudaFuncAttributeMaxDynamicSharedMemorySize, 99328);
    cudaFuncSetAttribute((const void*)k_mma<3, 256>, cudaFuncAttributeMaxDynamicSharedMemorySize, 98304);

    dim3 T(256);
    const size_t QK_Z = (size_t)BHN * SEQ * DIM;

    // 1: fused prep
    k_prep<<<3840, T>>>(x, Wq, Wk, Wv, xhf, xlf, xTf, wqktf, wvtf);

    // 2: Q+K projections merged (z=0 -> Qf, z=1 -> Kf), fp16 2-product
    k_mma<4, 128><<<dim3(8, 64, 2), T, 98304>>>((const uint8_t*)xhf, (const uint8_t*)xlf,
        (const uint8_t*)wqktf, 256, 256, 256,
        0, (size_t)HD * DIM, 0, nullptr, QKf, nullptr, nullptr, nullptr, QK_Z);

    // 3: scores -> exp fp16 (Ef) + row partial sums
    k_mma<1, 128><<<dim3(16, 16, BHN), T, 98304>>>((const uint8_t*)QKf, nullptr,
        (const uint8_t*)(QKf + QK_Z), 256, 256, 256,
        (size_t)SEQ * DIM, (size_t)SEQ * DIM, 0,
        part, Ef, nullptr, nullptr, nullptr, (size_t)SEQ * SEQ);

    // 4: PV (reads Ef; computes inv in-kernel; probs emission split by chunk parity;
    //        att rows scaled by inv)
    k_mma<2, 128><<<dim3(2, 16, BHN), T, 99328>>>((const uint8_t*)Ef, nullptr,
        (const uint8_t*)xTf, 2048, 2048, 2048,
        (size_t)SEQ * SEQ, (size_t)DIM * SEQ, 2,
        probs, attf, part, nullptr, nullptr, (size_t)SEQ * SEQ);

    // 5: att @ Wv + x -> LayerNorm -> out, fused epilogue
    k_mma<3, 256><<<dim3(1, 64, 1), T, 98304>>>((const uint8_t*)attf, nullptr,
        (const uint8_t*)wvtf, 1024, 1024, 1024,
        0, 0, 0, outp, nullptr, x, gamma, beta, 0);
}

// round 17
// speedup vs baseline: 1.1716x; 1.0511x over previous
#include <cuda_runtime.h>
#include <cuda_bf16.h>
#include <cuda_fp16.h>
#include <cstdint>
#include <cstddef>

#define BS   4
#define SEQ  2048
#define DIM  256
#define HH   4
#define HD   1024
#define BHN  16

// ======================= device scratch =======================
__device__ __align__(256) __half g_xhf [(size_t)BS*SEQ*DIM];
__device__ __align__(256) __half g_xlf [(size_t)BS*SEQ*DIM];
__device__ __align__(256) __half g_xTf [(size_t)BS*DIM*SEQ];
__device__ __align__(256) __half g_wqktf[(size_t)2*HD*DIM];
__device__ __align__(256) __half g_wvtf[(size_t)DIM*HD];
__device__ __align__(256) __half g_QKf [(size_t)2*BHN*SEQ*DIM];
__device__ __align__(256) __half g_Ef  [(size_t)BHN*SEQ*SEQ];     // fp16 exp(scores)
__device__ __align__(256) float  g_part[(size_t)BHN*16*SEQ];      // per-jtile row partials
__device__ __align__(256) __half g_attf[(size_t)BS*SEQ*HD];
__device__ __align__(256) float  g_out_fb [(size_t)BS*SEQ*DIM];
__device__ __align__(256) float  g_probs_fb[(size_t)BHN*SEQ*SEQ];

// ======================= helpers =======================
__device__ __forceinline__ uint32_t smem_u32(const void* p) {
    uint32_t a;
    asm("{ .reg .u64 t; cvta.to.shared.u64 t, %1; cvt.u32.u64 %0, t; }" : "=r"(a) : "l"(p));
    return a;
}
#define CP16(dst, src) \
    asm volatile("cp.async.cg.shared.global [%0], [%1], 16;" :: "r"(dst), "l"(src))
#define CP_COMMIT() asm volatile("cp.async.commit_group;" ::: "memory")
#define CP_WAIT0()  asm volatile("cp.async.wait_group 0;" ::: "memory")
#define CP_WAIT1()  asm volatile("cp.async.wait_group 1;" ::: "memory")

#define LDSM4(r0, r1, r2, r3, a) \
    asm volatile("ldmatrix.sync.aligned.m8n8.x4.shared.b16 {%0,%1,%2,%3}, [%4];" \
        : "=r"(r0), "=r"(r1), "=r"(r2), "=r"(r3) : "r"(a))

#define MMA_FP16(d, a, b) \
    asm volatile("mma.sync.aligned.m16n8k16.row.col.f32.f16.f16.f32 " \
        "{%0,%1,%2,%3}, {%4,%5,%6,%7}, {%8,%9}, {%0,%1,%2,%3};" \
        : "+f"((d)[0]), "+f"((d)[1]), "+f"((d)[2]), "+f"((d)[3]) \
        : "r"((a)[0]), "r"((a)[1]), "r"((a)[2]), "r"((a)[3]), \
          "r"((b)[0]), "r"((b)[1]))

// ======================= fused prep kernel =======================
__global__ void k_prep(const float* __restrict__ x, const float* __restrict__ Wq,
                       const float* __restrict__ Wk, const float* __restrict__ Wv,
                       __half* __restrict__ xhf, __half* __restrict__ xlf,
                       __half* __restrict__ xTf,
                       __half* __restrict__ wqktf, __half* __restrict__ wvtf)
{
    int b = blockIdx.x;
    const int tid = threadIdx.x;
    if (b < 1024) {
        int i0 = b * 2048 + tid;
#pragma unroll
        for (int q = 0; q < 8; ++q) {
            int i = i0 + q * 256;
            float v = x[i];
            __half h = __float2half_rn(v);
            __half l = __float2half_rn(v - __half2float(h));
            xhf[i] = h; xlf[i] = l;
        }
        return;
    }
    b -= 1024;
    const float* in; int R, C, bx, by;
    __half* oh;
    if (b < 256)      { in = Wq; oh = wqktf; R = 256;  C = 1024; bx = b & 31; by = b >> 5; }
    else if (b < 512) { b -= 256; in = Wk; oh = wqktf + (size_t)HD * DIM;
                        R = 256; C = 1024; bx = b & 31; by = b >> 5; }
    else if (b < 768) { b -= 512; in = Wv; oh = wvtf; R = 1024; C = 256; bx = b & 7; by = b >> 3; }
    else {
        b -= 768;
        int z = b >> 9, t = b & 511;
        in = x + (size_t)z * SEQ * DIM;
        oh = xTf + (size_t)z * DIM * SEQ;
        R = 2048; C = 256; bx = t & 7; by = t >> 3;
    }

    __shared__ float tbuf[32][33];
    const int tx = tid & 31, ty = tid >> 5;
    const int c0 = bx * 32, r0 = by * 32;
#pragma unroll
    for (int i = 0; i < 4; ++i)
        tbuf[ty + i * 8][tx] = in[(size_t)(r0 + ty + i * 8) * C + c0 + tx];
    __syncthreads();
#pragma unroll
    for (int i = 0; i < 4; ++i) {
        float v = tbuf[tx][ty + i * 8];
        oh[(size_t)(c0 + ty + i * 8) * R + r0 + tx] = __float2half_rn(v);
    }
}

// ======================= warp-MMA GEMM, cp.async pipeline, Kc=64 ====================
// MODE 4: proj Q+K (fp16 A-split 2-product, 2-stage, BM=128, BN=128, 2 CTA/SM)
// MODE 1: scores (fp16 1-product, 3-stage, BM=128, BN=128) -> exp(s/16) + partials
// MODE 2: pv     (fp16 1-product, 3-stage, BM=128, BN=128) -> fp16 att * inv;
//                probs emission via LDG (chunk-parity split across x-blocks)
// MODE 3: wv     (fp16 1-product, 2-stage, BM=64,  BN=256) -> residual + fused LN
template<int MODE, int BN>
__global__ void __launch_bounds__(256, (BN == 256) ? 1 : 2)
k_mma(const uint8_t* __restrict__ Ah, const uint8_t* __restrict__ Al,
      const uint8_t* __restrict__ Bh,
      int lda, int ldb, int K,
      size_t strideAz, size_t strideBz, int bShift,
      float* __restrict__ ep_f, void* __restrict__ ep_a,
      const float* __restrict__ resid,
      const float* __restrict__ gamma, const float* __restrict__ beta,
      size_t strideEz)
{
    constexpr bool PROJ   = (MODE == 4);
    constexpr int  NBM    = (MODE == 3) ? 2 : 4;       // warp m-subtiles (BM = NBM*32)
    constexpr int  BM     = NBM * 32;
    constexpr int  ATB    = BM * 128;                  // A tile bytes per stage
    constexpr int  WNT    = BN / 4;
    constexpr int  NBN    = BN / 32;
    constexpr int  NBL    = BN / 64;
    constexpr int  STAGE  = PROJ ? 49152 : (ATB + BN * 128);
    constexpr int  NSTAGE = (!PROJ && BN == 128) ? 3 : 2;
    extern __shared__ __align__(1024) char smem[];
    const uint32_t sb = smem_u32(smem);
    const int tid = threadIdx.x;
    const int wid = tid >> 5, lane = tid & 31;
    const int wm = wid >> 2, wn = wid & 3;
    const int mBase = blockIdx.y * BM, nBase = blockIdx.x * BN;
    const int z = blockIdx.z;

    const uint8_t* A0 = Ah + (size_t)z * strideAz * 2;
    const uint8_t* A1 = PROJ ? Al + (size_t)z * strideAz * 2 : nullptr;
    const uint8_t* B0 = Bh + (size_t)(z >> bShift) * strideBz * 2;

    const int nch = K >> 6;

    // MODE 2: per-row inverse sums (deterministic fixed-order)
    float* sinv = reinterpret_cast<float*>(smem + NSTAGE * STAGE);
    if (MODE == 2 && tid < 128) {
        const float* pp = resid + (size_t)z * 16 * SEQ + (mBase + tid);
        float s = 0.f;
#pragma unroll
        for (int jt = 0; jt < 16; ++jt) s += pp[(size_t)jt * SEQ];
        sinv[tid] = 1.0f / s;
    }

#define LOAD_TILE(srcB, ldE, rowB, k0, dstOff, ROWS)                                  \
    { _Pragma("unroll") for (int p_ = 0; p_ < (ROWS) / 32; ++p_) {                    \
        int idx_ = tid + 256 * p_;                                                    \
        int row_ = idx_ >> 3, c16_ = idx_ & 7;                                        \
        const uint8_t* g_ = (srcB) +                                                  \
            ((size_t)((rowB) + row_) * (ldE) + (k0) + c16_ * 8) * 2;                  \
        uint32_t d_ = sb + (dstOff) + row_ * 128 +                                    \
                      ((c16_ * 16) ^ ((row_ & 7) << 4));                              \
        CP16(d_, g_); } }

#define LOAD_CHUNK(i_, s_)                                                            \
    {                                                                                 \
        const int k0_ = (i_) * 64;                                                    \
        const int so_ = (s_) * STAGE;                                                 \
        if (PROJ) {                                                                   \
            LOAD_TILE(A0, lda, mBase, k0_, so_, 128);                                 \
            LOAD_TILE(A1, lda, mBase, k0_, so_ + 16384, 128);                         \
            LOAD_TILE(B0, ldb, nBase, k0_, so_ + 32768, 128);                         \
        } else {                                                                      \
            LOAD_TILE(A0, lda, mBase, k0_, so_, BM);                                  \
            LOAD_TILE(B0, ldb, nBase, k0_, so_ + ATB, BN);                            \
        }                                                                             \
        CP_COMMIT();                                                                  \
    }

    const int lrow = (lane & 7) + ((lane >> 3) & 1) * 8;
    const int kh16 = ((lane >> 4) & 1) * 16;
    const int swz  = (lane & 7) << 4;
    int rA[NBM], rB[NBL];
#pragma unroll
    for (int bm = 0; bm < NBM; ++bm) rA[bm] = (wm * (NBM * 16) + bm * 16 + lrow) * 128;
#pragma unroll
    for (int nb = 0; nb < NBL; ++nb) rB[nb] = (wn * WNT + nb * 16 + lrow) * 128;

    float acc[NBM][NBN][4];
#pragma unroll
    for (int a = 0; a < NBM; ++a)
#pragma unroll
        for (int b = 0; b < NBN; ++b)
#pragma unroll
            for (int c = 0; c < 4; ++c) acc[a][b][c] = 0.f;

#pragma unroll
    for (int p = 0; p < NSTAGE - 1; ++p)
        if (p < nch) LOAD_CHUNK(p, p);

    int st = 0;
    for (int i = 0; i < nch; ++i) {
        const int rem = nch - 1 - i;
        if (NSTAGE == 3) {
            if (rem >= 1) { CP_WAIT1(); } else { CP_WAIT0(); }
        } else {
            CP_WAIT0();
        }
        __syncthreads();
        if (i + NSTAGE - 1 < nch) {
            int s2 = st + NSTAGE - 1; if (s2 >= NSTAGE) s2 -= NSTAGE;
            LOAD_CHUNK(i + NSTAGE - 1, s2);
        }

        // MODE 2: emit fp32 probs for this chunk via gmem LDG (not smem),
        // split by chunk parity across the two x-blocks
        if (MODE == 2 && (int)blockIdx.x == (i & 1)) {
            const int k0 = i * 64;
#pragma unroll
            for (int p = 0; p < 4; ++p) {
                int idx = tid + 256 * p;
                int row = idx >> 3, c16 = idx & 7;
                const uint4 u = *reinterpret_cast<const uint4*>(
                    A0 + ((size_t)(mBase + row) * lda + k0 + c16 * 8) * 2);
                const float iv = sinv[row];
                float2 f0 = __half22float2(*reinterpret_cast<const __half2*>(&u.x));
                float2 f1 = __half22float2(*reinterpret_cast<const __half2*>(&u.y));
                float2 f2 = __half22float2(*reinterpret_cast<const __half2*>(&u.z));
                float2 f3 = __half22float2(*reinterpret_cast<const __half2*>(&u.w));
                float4 o0, o1;
                o0.x = f0.x * iv; o0.y = f0.y * iv; o0.z = f1.x * iv; o0.w = f1.y * iv;
                o1.x = f2.x * iv; o1.y = f2.y * iv; o1.z = f3.x * iv; o1.w = f3.y * iv;
                float* dst = ep_f + (size_t)z * strideEz +
                             (size_t)(mBase + row) * SEQ + k0 + c16 * 8;
                *reinterpret_cast<float4*>(dst)     = o0;
                *reinterpret_cast<float4*>(dst + 4) = o1;
            }
        }

        const uint32_t so = sb + st * STAGE;
        const uint32_t sA  = so;
        const uint32_t sAl = so + 16384;                   // PROJ only
        const uint32_t sB  = so + (PROJ ? 32768 : ATB);

#pragma unroll
        for (int ks = 0; ks < 4; ++ks) {
            const int cz = ((ks * 32) + kh16) ^ swz;
            uint32_t ah[NBM][4];
#pragma unroll
            for (int bm = 0; bm < NBM; ++bm)
                LDSM4(ah[bm][0], ah[bm][1], ah[bm][2], ah[bm][3], sA + rA[bm] + cz);
            uint32_t bh[NBN][2];
#pragma unroll
            for (int nb = 0; nb < NBL; ++nb) {
                uint32_t t0, t1, t2, t3;
                LDSM4(t0, t1, t2, t3, sB + rB[nb] + cz);
                bh[nb * 2][0] = t0; bh[nb * 2][1] = t2;
                bh[nb * 2 + 1][0] = t1; bh[nb * 2 + 1][1] = t3;
            }
#pragma unroll
            for (int bm = 0; bm < NBM; ++bm)
#pragma unroll
                for (int bn = 0; bn < NBN; ++bn) MMA_FP16(acc[bm][bn], ah[bm], bh[bn]);
            if (PROJ) {
                uint32_t al[NBM][4];
#pragma unroll
                for (int bm = 0; bm < NBM; ++bm)
                    LDSM4(al[bm][0], al[bm][1], al[bm][2], al[bm][3], sAl + rA[bm] + cz);
#pragma unroll
                for (int bm = 0; bm < NBM; ++bm)
#pragma unroll
                    for (int bn = 0; bn < NBN; ++bn) MMA_FP16(acc[bm][bn], al[bm], bh[bn]);
            }
        }
        if (++st == NSTAGE) st = 0;
        if (i + 1 < nch) __syncthreads();
    }
#undef LOAD_CHUNK
#undef LOAD_TILE

    // ======================= epilogue =======================
    const int g4 = lane >> 2, t4 = lane & 3;

    if (MODE == 1) {
        // exp(s/16) -> fp16 Ef + deterministic per-CTA row partial sums
        __syncthreads();
        float* rowp = reinterpret_cast<float*>(smem);   // [128][4]
        float rp[2 * NBM];
#pragma unroll
        for (int r8 = 0; r8 < 2 * NBM; ++r8) rp[r8] = 0.f;
#pragma unroll
        for (int bm = 0; bm < NBM; ++bm)
#pragma unroll
            for (int half = 0; half < 2; ++half) {
                const int gr = mBase + wm * (NBM * 16) + bm * 16 + g4 + half * 8;
                const int r8 = bm * 2 + half;
#pragma unroll
                for (int bn = 0; bn < NBN; ++bn) {
                    const int c0 = nBase + wn * WNT + bn * 8 + t4 * 2;
                    float e0 = __expf(acc[bm][bn][half * 2 + 0] * 0.0625f);
                    float e1 = __expf(acc[bm][bn][half * 2 + 1] * 0.0625f);
                    *reinterpret_cast<__half2*>((__half*)ep_a +
                        (size_t)z * strideEz + (size_t)gr * SEQ + c0) =
                        __floats2half2_rn(e0, e1);
                    rp[r8] += e0 + e1;
                }
            }
#pragma unroll
        for (int r8 = 0; r8 < 2 * NBM; ++r8) {
            rp[r8] += __shfl_xor_sync(~0u, rp[r8], 1);
            rp[r8] += __shfl_xor_sync(~0u, rp[r8], 2);
        }
        if (t4 == 0) {
#pragma unroll
            for (int bm = 0; bm < NBM; ++bm)
#pragma unroll
                for (int half = 0; half < 2; ++half) {
                    const int lr = wm * (NBM * 16) + bm * 16 + g4 + half * 8;
                    rowp[lr * 4 + wn] = rp[bm * 2 + half];
                }
        }
        __syncthreads();
        if (tid < BM) {
            float s = rowp[tid * 4] + rowp[tid * 4 + 1]
                    + rowp[tid * 4 + 2] + rowp[tid * 4 + 3];
            ep_f[((size_t)z * 16 + blockIdx.x) * SEQ + mBase + tid] = s;
        }
        return;
    }

    if (MODE == 3) {
        // ---- fused residual + LayerNorm (BN == 256 covers the full row) ----
        __syncthreads();
        float2* part = reinterpret_cast<float2*>(smem);              // [BM][16]
        float*  musg = reinterpret_cast<float*>(smem + BM * 16 * 8); // [BM][2]
        const int slice = wn * 4 + t4;

        float psum[2 * NBM], psq[2 * NBM];
#pragma unroll
        for (int r8 = 0; r8 < 2 * NBM; ++r8) { psum[r8] = 0.f; psq[r8] = 0.f; }
#pragma unroll
        for (int bm = 0; bm < NBM; ++bm)
#pragma unroll
            for (int half = 0; half < 2; ++half) {
                const int gr = mBase + wm * (NBM * 16) + bm * 16 + g4 + half * 8;
                const int r8 = bm * 2 + half;
#pragma unroll
                for (int bn = 0; bn < NBN; ++bn) {
                    const int c0 = wn * WNT + bn * 8 + t4 * 2;
                    float2 rx = *reinterpret_cast<const float2*>(
                        resid + (size_t)gr * DIM + c0);
                    float v0 = acc[bm][bn][half * 2 + 0] + rx.x;
                    float v1 = acc[bm][bn][half * 2 + 1] + rx.y;
                    psum[r8] += v0 + v1;
                    psq[r8]  += v0 * v0 + v1 * v1;
                }
            }
#pragma unroll
        for (int bm = 0; bm < NBM; ++bm)
#pragma unroll
            for (int half = 0; half < 2; ++half) {
                const int lr = wm * (NBM * 16) + bm * 16 + g4 + half * 8;
                const int r8 = bm * 2 + half;
                float2 p; p.x = psum[r8]; p.y = psq[r8];
                part[lr * 16 + slice] = p;
            }
        __syncthreads();
        if (tid < BM) {
            float s = 0.f, q = 0.f;
#pragma unroll
            for (int k = 0; k < 16; ++k) {
                float2 p = part[tid * 16 + k];
                s += p.x; q += p.y;
            }
            float mu  = s * (1.0f / 256.0f);
            float var = q * (1.0f / 256.0f) - mu * mu;
            musg[tid * 2]     = mu;
            musg[tid * 2 + 1] = rsqrtf(var + 1e-5f);
        }
        __syncthreads();
#pragma unroll
        for (int bm = 0; bm < NBM; ++bm)
#pragma unroll
            for (int half = 0; half < 2; ++half) {
                const int lr = wm * (NBM * 16) + bm * 16 + g4 + half * 8;
                const int gr = mBase + lr;
                const float mu  = musg[lr * 2];
                const float inv = musg[lr * 2 + 1];
#pragma unroll
                for (int bn = 0; bn < NBN; ++bn) {
                    const int c0 = wn * WNT + bn * 8 + t4 * 2;
                    size_t off = (size_t)gr * DIM + c0;
                    float2 rx = *reinterpret_cast<const float2*>(resid + off);
                    float v0 = acc[bm][bn][half * 2 + 0] + rx.x;
                    float v1 = acc[bm][bn][half * 2 + 1] + rx.y;
                    float2 gb0 = *reinterpret_cast<const float2*>(gamma + c0);
                    float2 bb0 = *reinterpret_cast<const float2*>(beta + c0);
                    float2 o;
                    o.x = (v0 - mu) * inv * gb0.x + bb0.x;
                    o.y = (v1 - mu) * inv * gb0.y + bb0.y;
                    *reinterpret_cast<float2*>(ep_f + off) = o;
                }
            }
        return;
    }

#pragma unroll
    for (int bm = 0; bm < NBM; ++bm) {
#pragma unroll
        for (int bn = 0; bn < NBN; ++bn) {
            const int r0 = mBase + wm * (NBM * 16) + bm * 16 + g4;
            const int c0 = nBase + wn * WNT + bn * 8 + t4 * 2;
            const float* a4 = acc[bm][bn];
#pragma unroll
            for (int half = 0; half < 2; ++half) {
                const int gr = r0 + half * 8;
                const float v0 = a4[half * 2 + 0];
                const float v1 = a4[half * 2 + 1];
                if (MODE == 4) {
                    const int bb = gr >> 11, rr = gr & 2047;
                    const int hh = rr >> 9, ib = (rr & 511) << 2;
                    const int ii = ib | (c0 >> 8), dd = c0 & 255;
                    size_t base = (size_t)z * strideEz +
                                  ((size_t)(bb * 4 + hh) * SEQ + ii) * DIM + dd;
                    *reinterpret_cast<__half2*>((__half*)ep_a + base) =
                        __floats2half2_rn(v0, v1);
                } else {  // MODE 2: att scaled by row inv (from smem)
                    const float sc = sinv[gr - mBase];
                    const int bb = z >> 2, h = z & 3;
                    size_t base = ((size_t)(bb * SEQ + gr)) * HD + h * DIM + c0;
                    *reinterpret_cast<__half2*>((__half*)ep_a + base) =
                        __floats2half2_rn(v0 * sc, v1 * sc);
                }
            }
        }
    }
}

// ======================= launch =======================
extern "C" void kernel_launch(void* const* d_in, const int* in_sizes, int n_in,
                              void* d_out, int out_size)
{
    const float* x     = (const float*)d_in[0];
    const float* Wq    = (const float*)d_in[1];
    const float* Wk    = (const float*)d_in[2];
    const float* Wv    = (const float*)d_in[3];
    const float* gamma = (const float*)d_in[4];
    const float* beta  = (const float*)d_in[5];

    __half *xhf, *xlf, *xTf, *wqktf, *wvtf, *QKf, *Ef, *attf;
    float *part, *outFb, *probsFb;
    cudaGetSymbolAddress((void**)&xhf, g_xhf);     cudaGetSymbolAddress((void**)&xlf, g_xlf);
    cudaGetSymbolAddress((void**)&xTf, g_xTf);
    cudaGetSymbolAddress((void**)&wqktf, g_wqktf); cudaGetSymbolAddress((void**)&wvtf, g_wvtf);
    cudaGetSymbolAddress((void**)&QKf, g_QKf);
    cudaGetSymbolAddress((void**)&Ef, g_Ef);
    cudaGetSymbolAddress((void**)&part, g_part);
    cudaGetSymbolAddress((void**)&attf, g_attf);
    cudaGetSymbolAddress((void**)&outFb, g_out_fb);
    cudaGetSymbolAddress((void**)&probsFb, g_probs_fb);

    const long long OUT_E = (long long)BS * SEQ * DIM;
    const long long PR_E  = (long long)BHN * SEQ * SEQ;
    long long osz = out_size;
    float *outp, *probs;
    if (osz >= OUT_E + PR_E) { outp = (float*)d_out; probs = (float*)d_out + OUT_E; }
    else if (osz >= PR_E)    { probs = (float*)d_out; outp = outFb; }
    else                     { outp = (float*)d_out; probs = probsFb; }

    cudaFuncSetAttribute((const void*)k_mma<4, 128>, cudaFuncAttributeMaxDynamicSharedMemorySize, 98304);
    cudaFuncSetAttribute((const void*)k_mma<1, 128>, cudaFuncAttributeMaxDynamicSharedMemorySize, 98304);
    cudaFuncSetAttribute((const void*)k_mma<2, 128>, cudaFuncAttributeMaxDynamicSharedMemorySize, 99328);
    cudaFuncSetAttribute((const void*)k_mma<3, 256>, cudaFuncAttributeMaxDynamicSharedMemorySize, 81920);

    dim3 T(256);
    const size_t QK_Z = (size_t)BHN * SEQ * DIM;

    // 1: fused prep
    k_prep<<<3840, T>>>(x, Wq, Wk, Wv, xhf, xlf, xTf, wqktf, wvtf);

    // 2: Q+K projections merged (z=0 -> Qf, z=1 -> Kf), fp16 2-product
    k_mma<4, 128><<<dim3(8, 64, 2), T, 98304>>>((const uint8_t*)xhf, (const uint8_t*)xlf,
        (const uint8_t*)wqktf, 256, 256, 256,
        0, (size_t)HD * DIM, 0, nullptr, QKf, nullptr, nullptr, nullptr, QK_Z);

    // 3: scores -> exp fp16 (Ef) + row partial sums
    k_mma<1, 128><<<dim3(16, 16, BHN), T, 98304>>>((const uint8_t*)QKf, nullptr,
        (const uint8_t*)(QKf + QK_Z), 256, 256, 256,
        (size_t)SEQ * DIM, (size_t)SEQ * DIM, 0,
        part, Ef, nullptr, nullptr, nullptr, (size_t)SEQ * SEQ);

    // 4: PV (reads Ef; inv in-kernel; probs emission via LDG, chunk-parity split;
    //        att rows scaled by inv)
    k_mma<2, 128><<<dim3(2, 16, BHN), T, 99328>>>((const uint8_t*)Ef, nullptr,
        (const uint8_t*)xTf, 2048, 2048, 2048,
        (size_t)SEQ * SEQ, (size_t)DIM * SEQ, 2,
        probs, attf, part, nullptr, nullptr, (size_t)SEQ * SEQ);

    // 5: att @ Wv + x -> LayerNorm -> out, fused epilogue (BM=64, 128 CTAs)
    k_mma<3, 256><<<dim3(1, 128, 1), T, 81920>>>((const uint8_t*)attf, nullptr,
        (const uint8_t*)wvtf, 1024, 1024, 1024,
        0, 0, 0, outp, nullptr, x, gamma, beta, 0);
}